// round 1
// baseline (speedup 1.0000x reference)
#include <cuda_runtime.h>
#include <math.h>

#define N_USERS 100000
#define N_ITEMS 50000
#define N_NODES 150000
#define D       64
#define NNZ     2000000
#define BATCH   256
#define WLAYER  0.25f   // 1/(N_LAYERS+1)

// ---------------- scratch (device globals; no allocations allowed) ----------
__device__ float g_cur[N_NODES * D];
__device__ float g_nxt[N_NODES * D];
__device__ float g_out[N_NODES * D];
__device__ float g_I[N_ITEMS * D];
__device__ float g_U[BATCH * D];
__device__ int   g_rowptr[N_NODES + 1];
__device__ int   g_wcur[N_NODES];
__device__ int   g_counts[N_NODES];
__device__ int   g_bsum[256];
__device__ int   g_boff[256];
__device__ int   g_csr_col[NNZ];
__device__ float g_csr_val[NNZ];

// ---------------- CSR build --------------------------------------------------
__global__ void k_zero_counts() {
    int i = blockIdx.x * blockDim.x + threadIdx.x;
    if (i < N_NODES) g_counts[i] = 0;
}

__global__ void k_hist(const int* __restrict__ rows) {
    int i = blockIdx.x * blockDim.x + threadIdx.x;
    if (i < NNZ) atomicAdd(&g_counts[rows[i]], 1);
}

__global__ void k_blockreduce() {
    __shared__ int sh[1024];
    int i = blockIdx.x * 1024 + threadIdx.x;
    sh[threadIdx.x] = (i < N_NODES) ? g_counts[i] : 0;
    __syncthreads();
    for (int s = 512; s > 0; s >>= 1) {
        if (threadIdx.x < s) sh[threadIdx.x] += sh[threadIdx.x + s];
        __syncthreads();
    }
    if (threadIdx.x == 0) g_bsum[blockIdx.x] = sh[0];
}

__global__ void k_scansums(int nb) {
    if (threadIdx.x == 0) {
        int acc = 0;
        for (int b = 0; b < nb; b++) { g_boff[b] = acc; acc += g_bsum[b]; }
    }
}

__global__ void k_blockscan() {
    __shared__ int sh[1024];
    int tid = threadIdx.x;
    int i = blockIdx.x * 1024 + tid;
    int v = (i < N_NODES) ? g_counts[i] : 0;
    sh[tid] = v;
    __syncthreads();
    for (int off = 1; off < 1024; off <<= 1) {
        int t = (tid >= off) ? sh[tid - off] : 0;
        __syncthreads();
        sh[tid] += t;
        __syncthreads();
    }
    if (i < N_NODES) {
        int excl = sh[tid] - v + g_boff[blockIdx.x];
        g_rowptr[i] = excl;
        g_wcur[i]   = excl;
    }
    if (i == 0) g_rowptr[N_NODES] = NNZ;
}

__global__ void k_scatter(const float* __restrict__ vals,
                          const int* __restrict__ rows,
                          const int* __restrict__ cols) {
    int i = blockIdx.x * blockDim.x + threadIdx.x;
    if (i < NNZ) {
        int r = rows[i];
        int pos = atomicAdd(&g_wcur[r], 1);
        g_csr_col[pos] = cols[i];
        g_csr_val[pos] = vals[i];
    }
}

// ---------------- embedding init: cur = emb, out = w*emb --------------------
__global__ void k_initemb(const float* __restrict__ ue, const float* __restrict__ ie) {
    int i = blockIdx.x * blockDim.x + threadIdx.x;
    if (i < N_USERS * D) {
        float v = ue[i];
        g_cur[i] = v; g_out[i] = v * WLAYER;
    } else if (i < N_NODES * D) {
        float v = ie[i - N_USERS * D];
        g_cur[i] = v; g_out[i] = v * WLAYER;
    }
}

// ---------------- SPMM: one warp per row; fused out += w*cur_next -----------
__global__ void k_spmm(int flip) {
    const float* __restrict__ ein = flip ? g_nxt : g_cur;
    float* __restrict__ eout      = flip ? g_cur : g_nxt;
    int w    = (blockIdx.x * blockDim.x + threadIdx.x) >> 5;
    int lane = threadIdx.x & 31;
    if (w >= N_NODES) return;
    int s = g_rowptr[w], e = g_rowptr[w + 1];
    float a0 = 0.f, a1 = 0.f;
    int i = s;
    for (; i + 1 < e; i += 2) {
        int c0 = g_csr_col[i], c1 = g_csr_col[i + 1];
        float v0 = g_csr_val[i], v1 = g_csr_val[i + 1];
        const float* p0 = ein + (size_t)c0 * D;
        const float* p1 = ein + (size_t)c1 * D;
        a0 += v0 * p0[lane]      + v1 * p1[lane];
        a1 += v0 * p0[lane + 32] + v1 * p1[lane + 32];
    }
    if (i < e) {
        int c = g_csr_col[i]; float v = g_csr_val[i];
        const float* p = ein + (size_t)c * D;
        a0 += v * p[lane];
        a1 += v * p[lane + 32];
    }
    int o = w * D;
    eout[o + lane]      = a0;
    eout[o + lane + 32] = a1;
    g_out[o + lane]      += WLAYER * a0;
    g_out[o + lane + 32] += WLAYER * a1;
}

// ---------------- items: gate MLP + fuse + item MLP (warp per 4 items) ------
__global__ void k_items(const float* __restrict__ pop_emb, const int* __restrict__ bins,
                        const float* __restrict__ gW1, const float* __restrict__ gb1,
                        const float* __restrict__ gW2, const float* __restrict__ gb2,
                        const float* __restrict__ iW1, const float* __restrict__ ib1,
                        const float* __restrict__ iW2, const float* __restrict__ ib2) {
    int w    = (blockIdx.x * blockDim.x + threadIdx.x) >> 5;
    int lane = threadIdx.x & 31;
    int it0  = w * 4;
    if (it0 >= N_ITEMS) return;
    const unsigned FULL = 0xffffffffu;

    float a_lo[4], a_hi[4], p_lo[4], p_hi[4];
#pragma unroll
    for (int i = 0; i < 4; i++) {
        int it = it0 + i;
        const float* ap = g_out + (size_t)(N_USERS + it) * D;
        a_lo[i] = ap[lane]; a_hi[i] = ap[lane + 32];
        int b = bins[it];
        p_lo[i] = pop_emb[b * D + lane];
        p_hi[i] = pop_emb[b * D + 32 + lane];
    }

    // gate hidden: h = gate_in(128) @ gW1(128x64)
    float h_lo[4] = {0, 0, 0, 0}, h_hi[4] = {0, 0, 0, 0};
#pragma unroll 4
    for (int k = 0; k < 32; k++) {
        float wlo = gW1[k * D + lane], whi = gW1[k * D + 32 + lane];
#pragma unroll
        for (int i = 0; i < 4; i++) {
            float xk = __shfl_sync(FULL, a_lo[i], k);
            h_lo[i] += xk * wlo; h_hi[i] += xk * whi;
        }
    }
#pragma unroll 4
    for (int k = 0; k < 32; k++) {
        float wlo = gW1[(k + 32) * D + lane], whi = gW1[(k + 32) * D + 32 + lane];
#pragma unroll
        for (int i = 0; i < 4; i++) {
            float xk = __shfl_sync(FULL, a_hi[i], k);
            h_lo[i] += xk * wlo; h_hi[i] += xk * whi;
        }
    }
#pragma unroll 4
    for (int k = 0; k < 32; k++) {
        float wlo = gW1[(k + 64) * D + lane], whi = gW1[(k + 64) * D + 32 + lane];
#pragma unroll
        for (int i = 0; i < 4; i++) {
            float xk = __shfl_sync(FULL, p_lo[i], k);
            h_lo[i] += xk * wlo; h_hi[i] += xk * whi;
        }
    }
#pragma unroll 4
    for (int k = 0; k < 32; k++) {
        float wlo = gW1[(k + 96) * D + lane], whi = gW1[(k + 96) * D + 32 + lane];
#pragma unroll
        for (int i = 0; i < 4; i++) {
            float xk = __shfl_sync(FULL, p_hi[i], k);
            h_lo[i] += xk * wlo; h_hi[i] += xk * whi;
        }
    }

    float b_lo = gb1[lane], b_hi = gb1[lane + 32];
    float w2lo = gW2[lane], w2hi = gW2[lane + 32];
    float gbias2 = gb2[0];
    float f_lo[4], f_hi[4];
#pragma unroll
    for (int i = 0; i < 4; i++) {
        float hl = fmaxf(h_lo[i] + b_lo, 0.f);
        float hh = fmaxf(h_hi[i] + b_hi, 0.f);
        float t = hl * w2lo + hh * w2hi;
#pragma unroll
        for (int off = 16; off > 0; off >>= 1) t += __shfl_xor_sync(FULL, t, off);
        float z = 1.f / (1.f + expf(-(t + gbias2)));
        f_lo[i] = (1.f - z) * a_lo[i] + z * p_lo[i];
        f_hi[i] = (1.f - z) * a_hi[i] + z * p_hi[i];
    }

    // item MLP layer 1
    float q_lo[4] = {0, 0, 0, 0}, q_hi[4] = {0, 0, 0, 0};
#pragma unroll 4
    for (int k = 0; k < 32; k++) {
        float wlo = iW1[k * D + lane], whi = iW1[k * D + 32 + lane];
#pragma unroll
        for (int i = 0; i < 4; i++) {
            float xk = __shfl_sync(FULL, f_lo[i], k);
            q_lo[i] += xk * wlo; q_hi[i] += xk * whi;
        }
    }
#pragma unroll 4
    for (int k = 0; k < 32; k++) {
        float wlo = iW1[(k + 32) * D + lane], whi = iW1[(k + 32) * D + 32 + lane];
#pragma unroll
        for (int i = 0; i < 4; i++) {
            float xk = __shfl_sync(FULL, f_hi[i], k);
            q_lo[i] += xk * wlo; q_hi[i] += xk * whi;
        }
    }
    float ib_lo = ib1[lane], ib_hi = ib1[lane + 32];
#pragma unroll
    for (int i = 0; i < 4; i++) {
        q_lo[i] = fmaxf(q_lo[i] + ib_lo, 0.f);
        q_hi[i] = fmaxf(q_hi[i] + ib_hi, 0.f);
    }

    // item MLP layer 2
    float y_lo[4] = {0, 0, 0, 0}, y_hi[4] = {0, 0, 0, 0};
#pragma unroll 4
    for (int k = 0; k < 32; k++) {
        float wlo = iW2[k * D + lane], whi = iW2[k * D + 32 + lane];
#pragma unroll
        for (int i = 0; i < 4; i++) {
            float xk = __shfl_sync(FULL, q_lo[i], k);
            y_lo[i] += xk * wlo; y_hi[i] += xk * whi;
        }
    }
#pragma unroll 4
    for (int k = 0; k < 32; k++) {
        float wlo = iW2[(k + 32) * D + lane], whi = iW2[(k + 32) * D + 32 + lane];
#pragma unroll
        for (int i = 0; i < 4; i++) {
            float xk = __shfl_sync(FULL, q_hi[i], k);
            y_lo[i] += xk * wlo; y_hi[i] += xk * whi;
        }
    }
    float ob_lo = ib2[lane], ob_hi = ib2[lane + 32];
#pragma unroll
    for (int i = 0; i < 4; i++) {
        int it = it0 + i;
        g_I[it * D + lane]      = y_lo[i] + ob_lo;
        g_I[it * D + lane + 32] = y_hi[i] + ob_hi;
    }
}

// ---------------- users: MLP on 256 gathered users (warp per user) ----------
__global__ void k_users(const int* __restrict__ users,
                        const float* __restrict__ uW1, const float* __restrict__ ub1,
                        const float* __restrict__ uW2, const float* __restrict__ ub2) {
    int w    = (blockIdx.x * blockDim.x + threadIdx.x) >> 5;
    int lane = threadIdx.x & 31;
    if (w >= BATCH) return;
    const unsigned FULL = 0xffffffffu;
    int u = users[w];
    const float* xp = g_out + (size_t)u * D;
    float x_lo = xp[lane], x_hi = xp[lane + 32];

    float h_lo = 0.f, h_hi = 0.f;
#pragma unroll 4
    for (int k = 0; k < 32; k++) {
        float xk = __shfl_sync(FULL, x_lo, k);
        h_lo += xk * uW1[k * D + lane];
        h_hi += xk * uW1[k * D + 32 + lane];
    }
#pragma unroll 4
    for (int k = 0; k < 32; k++) {
        float xk = __shfl_sync(FULL, x_hi, k);
        h_lo += xk * uW1[(k + 32) * D + lane];
        h_hi += xk * uW1[(k + 32) * D + 32 + lane];
    }
    h_lo = fmaxf(h_lo + ub1[lane], 0.f);
    h_hi = fmaxf(h_hi + ub1[lane + 32], 0.f);

    float y_lo = 0.f, y_hi = 0.f;
#pragma unroll 4
    for (int k = 0; k < 32; k++) {
        float xk = __shfl_sync(FULL, h_lo, k);
        y_lo += xk * uW2[k * D + lane];
        y_hi += xk * uW2[k * D + 32 + lane];
    }
#pragma unroll 4
    for (int k = 0; k < 32; k++) {
        float xk = __shfl_sync(FULL, h_hi, k);
        y_lo += xk * uW2[(k + 32) * D + lane];
        y_hi += xk * uW2[(k + 32) * D + 32 + lane];
    }
    g_U[w * D + lane]      = y_lo + ub2[lane];
    g_U[w * D + lane + 32] = y_hi + ub2[lane + 32];
}

// ---------------- scores: [256,64] @ [50000,64]^T + biases ------------------
__global__ void k_scores(const float* __restrict__ user_bias,
                         const float* __restrict__ item_bias,
                         const int* __restrict__ users,
                         float* __restrict__ out) {
    __shared__ float Us[64][65];
    __shared__ float Is[64][65];
    int tid = threadIdx.x;           // 256 threads
    int tx = tid & 15;               // item dir
    int ty = tid >> 4;               // user dir
    int m0 = blockIdx.y * 64;        // user tile base (0..192)
    int n0 = blockIdx.x * 64;        // item tile base

    for (int idx = tid; idx < 64 * 64; idx += 256) {
        int r = idx >> 6, k = idx & 63;
        Us[r][k] = g_U[(m0 + r) * D + k];
        int n = n0 + r;
        Is[r][k] = (n < N_ITEMS) ? g_I[n * D + k] : 0.f;
    }
    __syncthreads();

    float acc[4][4] = {};
#pragma unroll 8
    for (int k = 0; k < 64; k++) {
        float uu[4], vv[4];
#pragma unroll
        for (int r = 0; r < 4; r++) uu[r] = Us[ty * 4 + r][k];
#pragma unroll
        for (int c = 0; c < 4; c++) vv[c] = Is[tx * 4 + c][k];
#pragma unroll
        for (int r = 0; r < 4; r++)
#pragma unroll
            for (int c = 0; c < 4; c++) acc[r][c] += uu[r] * vv[c];
    }

#pragma unroll
    for (int r = 0; r < 4; r++) {
        int m = m0 + ty * 4 + r;
        float ub = user_bias[users[m]];
#pragma unroll
        for (int c = 0; c < 4; c++) {
            int n = n0 + tx * 4 + c;
            if (n < N_ITEMS)
                out[(size_t)m * N_ITEMS + n] = acc[r][c] + ub + item_bias[n];
        }
    }
}

// ---------------- launch -----------------------------------------------------
extern "C" void kernel_launch(void* const* d_in, const int* in_sizes, int n_in,
                              void* d_out, int out_size) {
    const float* user_emb  = (const float*)d_in[0];
    const float* item_emb  = (const float*)d_in[1];
    const float* user_bias = (const float*)d_in[2];
    const float* item_bias = (const float*)d_in[3];
    const float* pop_emb   = (const float*)d_in[4];
    const float* uW1 = (const float*)d_in[5];
    const float* ub1 = (const float*)d_in[6];
    const float* uW2 = (const float*)d_in[7];
    const float* ub2 = (const float*)d_in[8];
    const float* iW1 = (const float*)d_in[9];
    const float* ib1 = (const float*)d_in[10];
    const float* iW2 = (const float*)d_in[11];
    const float* ib2 = (const float*)d_in[12];
    const float* gW1 = (const float*)d_in[13];
    const float* gb1 = (const float*)d_in[14];
    const float* gW2 = (const float*)d_in[15];
    const float* gb2 = (const float*)d_in[16];
    const float* adj_vals = (const float*)d_in[17];
    const int*   adj_rows = (const int*)d_in[18];
    const int*   adj_cols = (const int*)d_in[19];
    const int*   bins     = (const int*)d_in[20];
    const int*   users    = (const int*)d_in[21];
    float* out = (float*)d_out;

    // CSR build
    k_zero_counts<<<(N_NODES + 255) / 256, 256>>>();
    k_hist<<<(NNZ + 255) / 256, 256>>>(adj_rows);
    int nb = (N_NODES + 1023) / 1024;
    k_blockreduce<<<nb, 1024>>>();
    k_scansums<<<1, 32>>>(nb);
    k_blockscan<<<nb, 1024>>>();
    k_scatter<<<(NNZ + 255) / 256, 256>>>(adj_vals, adj_rows, adj_cols);

    // init cur = emb, out = w*emb
    k_initemb<<<(N_NODES * D + 255) / 256, 256>>>(user_emb, item_emb);

    // 3 propagation layers (ping-pong), out += w*cur each layer (fused)
    int spmmBlocks = (N_NODES * 32 + 255) / 256;
    k_spmm<<<spmmBlocks, 256>>>(0);   // cur -> nxt
    k_spmm<<<spmmBlocks, 256>>>(1);   // nxt -> cur
    k_spmm<<<spmmBlocks, 256>>>(0);   // cur -> nxt

    // items: gate + fuse + item MLP
    int itemWarps = N_ITEMS / 4;                     // 12500
    k_items<<<(itemWarps * 32 + 255) / 256, 256>>>(pop_emb, bins,
                                                   gW1, gb1, gW2, gb2,
                                                   iW1, ib1, iW2, ib2);
    // users MLP
    k_users<<<(BATCH * 32 + 255) / 256, 256>>>(users, uW1, ub1, uW2, ub2);

    // scores
    dim3 grid((N_ITEMS + 63) / 64, BATCH / 64);
    k_scores<<<grid, 256>>>(user_bias, item_bias, users, out);
}

// round 2
// speedup vs baseline: 1.1809x; 1.1809x over previous
#include <cuda_runtime.h>
#include <math.h>

#define N_USERS 100000
#define N_ITEMS 50000
#define N_NODES 150000
#define D       64
#define NNZ     2000000
#define BATCH   256
#define WL      0.25f   // 1/(N_LAYERS+1)

// ---------------- scratch (device globals) -----------------------------------
__device__ __align__(256) float g_e1[N_NODES * D];
__device__ __align__(256) float g_e2[N_NODES * D];
__device__ __align__(256) float g_outI[N_ITEMS * D];
__device__ __align__(256) float g_I[N_ITEMS * D];
__device__ __align__(256) float g_U[BATCH * D];
__device__ int   g_rowptr[N_NODES + 1];
__device__ int   g_wcur[N_NODES];
__device__ int   g_counts[N_NODES];
__device__ int   g_bsum[256];
__device__ __align__(256) int2 g_csr[NNZ];

// ---------------- CSR build ---------------------------------------------------
__global__ void k_zero_counts() {
    int i = blockIdx.x * blockDim.x + threadIdx.x;
    if (i < N_NODES) g_counts[i] = 0;
}

__global__ void k_hist(const int* __restrict__ rows) {
    int i = blockIdx.x * blockDim.x + threadIdx.x;
    if (i < NNZ) atomicAdd(&g_counts[rows[i]], 1);
}

__global__ void k_blockreduce() {
    __shared__ int sh[1024];
    int i = blockIdx.x * 1024 + threadIdx.x;
    sh[threadIdx.x] = (i < N_NODES) ? g_counts[i] : 0;
    __syncthreads();
    for (int s = 512; s > 0; s >>= 1) {
        if (threadIdx.x < s) sh[threadIdx.x] += sh[threadIdx.x + s];
        __syncthreads();
    }
    if (threadIdx.x == 0) g_bsum[blockIdx.x] = sh[0];
}

// fused: each block computes its own prefix of block sums, then scans its chunk
__global__ void k_blockscan() {
    __shared__ int sh[1024];
    __shared__ int soff;
    int tid = threadIdx.x;

    // prefix of block sums [0, blockIdx.x)
    sh[tid] = (tid < blockIdx.x) ? g_bsum[tid] : 0;
    __syncthreads();
    for (int s = 512; s > 0; s >>= 1) {
        if (tid < s) sh[tid] += sh[tid + s];
        __syncthreads();
    }
    if (tid == 0) soff = sh[0];
    __syncthreads();

    int i = blockIdx.x * 1024 + tid;
    int v = (i < N_NODES) ? g_counts[i] : 0;
    sh[tid] = v;
    __syncthreads();
    for (int off = 1; off < 1024; off <<= 1) {
        int t = (tid >= off) ? sh[tid - off] : 0;
        __syncthreads();
        sh[tid] += t;
        __syncthreads();
    }
    if (i < N_NODES) {
        int excl = sh[tid] - v + soff;
        g_rowptr[i] = excl;
        g_wcur[i]   = excl;
    }
    if (i == 0) g_rowptr[N_NODES] = NNZ;
}

__global__ void k_scatter(const float* __restrict__ vals,
                          const int* __restrict__ rows,
                          const int* __restrict__ cols) {
    int i = blockIdx.x * blockDim.x + threadIdx.x;
    if (i < NNZ) {
        int r = rows[i];
        int pos = atomicAdd(&g_wcur[r], 1);
        g_csr[pos] = make_int2(cols[i], __float_as_int(vals[i]));
    }
}

// ---------------- SPMM over all nodes (layers 1 & 2) --------------------------
__device__ __forceinline__ const float* node_ptr(int c, const float* inU, const float* inI) {
    return (c < N_USERS) ? (inU + (size_t)c * D) : (inI + (size_t)(c - N_USERS) * D);
}

__global__ void k_spmm(const float* __restrict__ inU, const float* __restrict__ inI,
                       float* __restrict__ eout) {
    int w    = (blockIdx.x * blockDim.x + threadIdx.x) >> 5;
    int lane = threadIdx.x & 31;
    if (w >= N_NODES) return;
    int s = __ldg(&g_rowptr[w]), e = __ldg(&g_rowptr[w + 1]);
    float ax = 0.f, ay = 0.f;
    int i = s;
    for (; i + 4 <= e; i += 4) {
        int2 c0 = g_csr[i], c1 = g_csr[i + 1], c2 = g_csr[i + 2], c3 = g_csr[i + 3];
        float2 x0 = ((const float2*)node_ptr(c0.x, inU, inI))[lane];
        float2 x1 = ((const float2*)node_ptr(c1.x, inU, inI))[lane];
        float2 x2 = ((const float2*)node_ptr(c2.x, inU, inI))[lane];
        float2 x3 = ((const float2*)node_ptr(c3.x, inU, inI))[lane];
        float v0 = __int_as_float(c0.y), v1 = __int_as_float(c1.y);
        float v2 = __int_as_float(c2.y), v3 = __int_as_float(c3.y);
        ax += v0 * x0.x + v1 * x1.x + v2 * x2.x + v3 * x3.x;
        ay += v0 * x0.y + v1 * x1.y + v2 * x2.y + v3 * x3.y;
    }
    for (; i < e; i++) {
        int2 c = g_csr[i];
        float2 x = ((const float2*)node_ptr(c.x, inU, inI))[lane];
        float v = __int_as_float(c.y);
        ax += v * x.x; ay += v * x.y;
    }
    ((float2*)(eout + (size_t)w * D))[lane] = make_float2(ax, ay);
}

// ---------------- layer-3 SPMM: item rows only, fused out epilogue ------------
__global__ void k_spmm_items(const float* __restrict__ item_emb) {
    int w    = (blockIdx.x * blockDim.x + threadIdx.x) >> 5;
    int lane = threadIdx.x & 31;
    if (w >= N_ITEMS) return;
    int node = N_USERS + w;
    int s = __ldg(&g_rowptr[node]), e = __ldg(&g_rowptr[node + 1]);
    float ax = 0.f, ay = 0.f;
    int i = s;
    for (; i + 4 <= e; i += 4) {
        int2 c0 = g_csr[i], c1 = g_csr[i + 1], c2 = g_csr[i + 2], c3 = g_csr[i + 3];
        float2 x0 = ((const float2*)(g_e2 + (size_t)c0.x * D))[lane];
        float2 x1 = ((const float2*)(g_e2 + (size_t)c1.x * D))[lane];
        float2 x2 = ((const float2*)(g_e2 + (size_t)c2.x * D))[lane];
        float2 x3 = ((const float2*)(g_e2 + (size_t)c3.x * D))[lane];
        float v0 = __int_as_float(c0.y), v1 = __int_as_float(c1.y);
        float v2 = __int_as_float(c2.y), v3 = __int_as_float(c3.y);
        ax += v0 * x0.x + v1 * x1.x + v2 * x2.x + v3 * x3.x;
        ay += v0 * x0.y + v1 * x1.y + v2 * x2.y + v3 * x3.y;
    }
    for (; i < e; i++) {
        int2 c = g_csr[i];
        float2 x = ((const float2*)(g_e2 + (size_t)c.x * D))[lane];
        float v = __int_as_float(c.y);
        ax += v * x.x; ay += v * x.y;
    }
    float2 e0 = ((const float2*)(item_emb + (size_t)w * D))[lane];
    float2 x1 = ((const float2*)(g_e1 + (size_t)node * D))[lane];
    float2 x2 = ((const float2*)(g_e2 + (size_t)node * D))[lane];
    ((float2*)(g_outI + (size_t)w * D))[lane] =
        make_float2(WL * (e0.x + x1.x + x2.x + ax), WL * (e0.y + x1.y + x2.y + ay));
}

// ---------------- items: gate MLP + fuse + item MLP (warp per 8 items) --------
__global__ void k_items(const float* __restrict__ pop_emb, const int* __restrict__ bins,
                        const float* __restrict__ gW1, const float* __restrict__ gb1,
                        const float* __restrict__ gW2, const float* __restrict__ gb2,
                        const float* __restrict__ iW1, const float* __restrict__ ib1,
                        const float* __restrict__ iW2, const float* __restrict__ ib2) {
    int w    = (blockIdx.x * blockDim.x + threadIdx.x) >> 5;
    int lane = threadIdx.x & 31;
    int it0  = w * 8;
    if (it0 >= N_ITEMS) return;
    const unsigned FULL = 0xffffffffu;

    float2 a[8], p[8];
#pragma unroll
    for (int i = 0; i < 8; i++) {
        a[i] = ((const float2*)(g_outI + (size_t)(it0 + i) * D))[lane];
        int b = __ldg(&bins[it0 + i]);
        p[i] = ((const float2*)(pop_emb + (size_t)b * D))[lane];
    }

    // gate hidden: h = [a(64), p(64)] @ gW1(128x64)
    float2 h[8];
#pragma unroll
    for (int i = 0; i < 8; i++) h[i] = make_float2(0.f, 0.f);
    const float2* GW = (const float2*)gW1;
#pragma unroll 4
    for (int m = 0; m < 32; m++) {
        float2 wA = GW[(2 * m) * 32 + lane];
        float2 wB = GW[(2 * m + 1) * 32 + lane];
#pragma unroll
        for (int i = 0; i < 8; i++) {
            float xA = __shfl_sync(FULL, a[i].x, m);
            float xB = __shfl_sync(FULL, a[i].y, m);
            h[i].x += xA * wA.x + xB * wB.x;
            h[i].y += xA * wA.y + xB * wB.y;
        }
    }
#pragma unroll 4
    for (int m = 0; m < 32; m++) {
        float2 wA = GW[(64 + 2 * m) * 32 + lane];
        float2 wB = GW[(65 + 2 * m) * 32 + lane];
#pragma unroll
        for (int i = 0; i < 8; i++) {
            float xA = __shfl_sync(FULL, p[i].x, m);
            float xB = __shfl_sync(FULL, p[i].y, m);
            h[i].x += xA * wA.x + xB * wB.x;
            h[i].y += xA * wA.y + xB * wB.y;
        }
    }

    float2 b1 = ((const float2*)gb1)[lane];
    float2 w2 = ((const float2*)gW2)[lane];
    float gbias2 = gb2[0];
    float2 f[8];
#pragma unroll
    for (int i = 0; i < 8; i++) {
        float hx = fmaxf(h[i].x + b1.x, 0.f);
        float hy = fmaxf(h[i].y + b1.y, 0.f);
        float t = hx * w2.x + hy * w2.y;
#pragma unroll
        for (int off = 16; off > 0; off >>= 1) t += __shfl_xor_sync(FULL, t, off);
        float z = 1.f / (1.f + expf(-(t + gbias2)));
        f[i].x = (1.f - z) * a[i].x + z * p[i].x;
        f[i].y = (1.f - z) * a[i].y + z * p[i].y;
    }

    // item MLP layer 1: q = relu(f @ iW1 + ib1)
    float2 q[8];
#pragma unroll
    for (int i = 0; i < 8; i++) q[i] = make_float2(0.f, 0.f);
    const float2* IW1 = (const float2*)iW1;
#pragma unroll 4
    for (int m = 0; m < 32; m++) {
        float2 wA = IW1[(2 * m) * 32 + lane];
        float2 wB = IW1[(2 * m + 1) * 32 + lane];
#pragma unroll
        for (int i = 0; i < 8; i++) {
            float xA = __shfl_sync(FULL, f[i].x, m);
            float xB = __shfl_sync(FULL, f[i].y, m);
            q[i].x += xA * wA.x + xB * wB.x;
            q[i].y += xA * wA.y + xB * wB.y;
        }
    }
    float2 ibv = ((const float2*)ib1)[lane];
#pragma unroll
    for (int i = 0; i < 8; i++) {
        q[i].x = fmaxf(q[i].x + ibv.x, 0.f);
        q[i].y = fmaxf(q[i].y + ibv.y, 0.f);
    }

    // item MLP layer 2: y = q @ iW2 + ib2
    float2 y[8];
#pragma unroll
    for (int i = 0; i < 8; i++) y[i] = make_float2(0.f, 0.f);
    const float2* IW2 = (const float2*)iW2;
#pragma unroll 4
    for (int m = 0; m < 32; m++) {
        float2 wA = IW2[(2 * m) * 32 + lane];
        float2 wB = IW2[(2 * m + 1) * 32 + lane];
#pragma unroll
        for (int i = 0; i < 8; i++) {
            float xA = __shfl_sync(FULL, q[i].x, m);
            float xB = __shfl_sync(FULL, q[i].y, m);
            y[i].x += xA * wA.x + xB * wB.x;
            y[i].y += xA * wA.y + xB * wB.y;
        }
    }
    float2 obv = ((const float2*)ib2)[lane];
#pragma unroll
    for (int i = 0; i < 8; i++) {
        ((float2*)(g_I + (size_t)(it0 + i) * D))[lane] =
            make_float2(y[i].x + obv.x, y[i].y + obv.y);
    }
}

// ---------------- users: e3 row + out + MLP (warp per user) -------------------
__global__ void k_users(const int* __restrict__ users, const float* __restrict__ user_emb,
                        const float* __restrict__ uW1, const float* __restrict__ ub1,
                        const float* __restrict__ uW2, const float* __restrict__ ub2) {
    int w    = (blockIdx.x * blockDim.x + threadIdx.x) >> 5;
    int lane = threadIdx.x & 31;
    if (w >= BATCH) return;
    const unsigned FULL = 0xffffffffu;
    int u = __ldg(&users[w]);
    int s = __ldg(&g_rowptr[u]), e = __ldg(&g_rowptr[u + 1]);
    float ax = 0.f, ay = 0.f;
    for (int i = s; i < e; i++) {
        int2 c = g_csr[i];
        float2 x = ((const float2*)(g_e2 + (size_t)c.x * D))[lane];
        float v = __int_as_float(c.y);
        ax += v * x.x; ay += v * x.y;
    }
    float2 e0 = ((const float2*)(user_emb + (size_t)u * D))[lane];
    float2 x1 = ((const float2*)(g_e1 + (size_t)u * D))[lane];
    float2 x2 = ((const float2*)(g_e2 + (size_t)u * D))[lane];
    float xx = WL * (e0.x + x1.x + x2.x + ax);
    float xy = WL * (e0.y + x1.y + x2.y + ay);

    const float2* W1 = (const float2*)uW1;
    float hx = 0.f, hy = 0.f;
#pragma unroll 8
    for (int m = 0; m < 32; m++) {
        float2 wA = W1[(2 * m) * 32 + lane];
        float2 wB = W1[(2 * m + 1) * 32 + lane];
        float xA = __shfl_sync(FULL, xx, m);
        float xB = __shfl_sync(FULL, xy, m);
        hx += xA * wA.x + xB * wB.x;
        hy += xA * wA.y + xB * wB.y;
    }
    float2 b1 = ((const float2*)ub1)[lane];
    hx = fmaxf(hx + b1.x, 0.f);
    hy = fmaxf(hy + b1.y, 0.f);

    const float2* W2 = (const float2*)uW2;
    float yx = 0.f, yy = 0.f;
#pragma unroll 8
    for (int m = 0; m < 32; m++) {
        float2 wA = W2[(2 * m) * 32 + lane];
        float2 wB = W2[(2 * m + 1) * 32 + lane];
        float xA = __shfl_sync(FULL, hx, m);
        float xB = __shfl_sync(FULL, hy, m);
        yx += xA * wA.x + xB * wB.x;
        yy += xA * wA.y + xB * wB.y;
    }
    float2 b2 = ((const float2*)ub2)[lane];
    ((float2*)(g_U + (size_t)w * D))[lane] = make_float2(yx + b2.x, yy + b2.y);
}

// ---------------- scores: [256,64] @ [50000,64]^T + biases --------------------
__global__ void k_scores(const float* __restrict__ user_bias,
                         const float* __restrict__ item_bias,
                         const int* __restrict__ users,
                         float* __restrict__ out) {
    __shared__ float Us[64][65];
    __shared__ float Is[64][65];
    int tid = threadIdx.x;           // 256 threads
    int tx = tid & 15;               // item dir
    int ty = tid >> 4;               // user dir
    int m0 = blockIdx.y * 64;        // user tile base
    int n0 = blockIdx.x * 64;        // item tile base

    for (int idx = tid; idx < 64 * 64; idx += 256) {
        int r = idx >> 6, k = idx & 63;
        Us[r][k] = g_U[(m0 + r) * D + k];
        int n = n0 + r;
        Is[r][k] = (n < N_ITEMS) ? g_I[(size_t)n * D + k] : 0.f;
    }
    __syncthreads();

    float acc[4][4] = {};
#pragma unroll 8
    for (int k = 0; k < 64; k++) {
        float uu[4], vv[4];
#pragma unroll
        for (int r = 0; r < 4; r++) uu[r] = Us[ty * 4 + r][k];
#pragma unroll
        for (int c = 0; c < 4; c++) vv[c] = Is[tx * 4 + c][k];
#pragma unroll
        for (int r = 0; r < 4; r++)
#pragma unroll
            for (int c = 0; c < 4; c++) acc[r][c] += uu[r] * vv[c];
    }

#pragma unroll
    for (int r = 0; r < 4; r++) {
        int m = m0 + ty * 4 + r;
        float ub = user_bias[users[m]];
#pragma unroll
        for (int c = 0; c < 4; c++) {
            int n = n0 + tx * 4 + c;
            if (n < N_ITEMS)
                out[(size_t)m * N_ITEMS + n] = acc[r][c] + ub + item_bias[n];
        }
    }
}

// ---------------- launch -------------------------------------------------------
extern "C" void kernel_launch(void* const* d_in, const int* in_sizes, int n_in,
                              void* d_out, int out_size) {
    const float* user_emb  = (const float*)d_in[0];
    const float* item_emb  = (const float*)d_in[1];
    const float* user_bias = (const float*)d_in[2];
    const float* item_bias = (const float*)d_in[3];
    const float* pop_emb   = (const float*)d_in[4];
    const float* uW1 = (const float*)d_in[5];
    const float* ub1 = (const float*)d_in[6];
    const float* uW2 = (const float*)d_in[7];
    const float* ub2 = (const float*)d_in[8];
    const float* iW1 = (const float*)d_in[9];
    const float* ib1 = (const float*)d_in[10];
    const float* iW2 = (const float*)d_in[11];
    const float* ib2 = (const float*)d_in[12];
    const float* gW1 = (const float*)d_in[13];
    const float* gb1 = (const float*)d_in[14];
    const float* gW2 = (const float*)d_in[15];
    const float* gb2 = (const float*)d_in[16];
    const float* adj_vals = (const float*)d_in[17];
    const int*   adj_rows = (const int*)d_in[18];
    const int*   adj_cols = (const int*)d_in[19];
    const int*   bins     = (const int*)d_in[20];
    const int*   users    = (const int*)d_in[21];
    float* out = (float*)d_out;

    // CSR build
    k_zero_counts<<<(N_NODES + 255) / 256, 256>>>();
    k_hist<<<(NNZ + 255) / 256, 256>>>(adj_rows);
    int nb = (N_NODES + 1023) / 1024;
    k_blockreduce<<<nb, 1024>>>();
    k_blockscan<<<nb, 1024>>>();
    k_scatter<<<(NNZ + 255) / 256, 256>>>(adj_vals, adj_rows, adj_cols);

    // resolve device-global addresses for aliased in/out across layers
    float* e1; cudaGetSymbolAddress((void**)&e1, g_e1);
    float* e2; cudaGetSymbolAddress((void**)&e2, g_e2);

    int fullBlocks = (N_NODES * 32 + 255) / 256;
    // layer 1: (user_emb|item_emb) -> e1
    k_spmm<<<fullBlocks, 256>>>(user_emb, item_emb, e1);
    // layer 2: e1 -> e2
    k_spmm<<<fullBlocks, 256>>>(e1, e1 + (size_t)N_USERS * D, e2);
    // layer 3: item rows only, fused out epilogue
    int itemBlocks = (N_ITEMS * 32 + 255) / 256;
    k_spmm_items<<<itemBlocks, 256>>>(item_emb);

    // items: gate + fuse + item MLP (warp per 8 items)
    int itemWarps = N_ITEMS / 8;  // 6250
    k_items<<<(itemWarps * 32 + 255) / 256, 256>>>(pop_emb, bins,
                                                   gW1, gb1, gW2, gb2,
                                                   iW1, ib1, iW2, ib2);
    // users: e3 row + out + MLP
    k_users<<<(BATCH * 32 + 255) / 256, 256>>>(users, user_emb, uW1, ub1, uW2, ub2);

    // scores
    dim3 grid((N_ITEMS + 63) / 64, BATCH / 64);
    k_scores<<<grid, 256>>>(user_bias, item_bias, users, out);
}

// round 3
// speedup vs baseline: 1.3315x; 1.1275x over previous
#include <cuda_runtime.h>
#include <math.h>

#define N_USERS 100000
#define N_ITEMS 50000
#define N_NODES 150000
#define D       64
#define NNZ     2000000
#define BATCH   256
#define WL      0.25f   // 1/(N_LAYERS+1)

typedef unsigned long long u64t;

// ---------------- f32x2 packed-FMA helpers (sm_100+) -------------------------
__device__ __forceinline__ u64t pack2(float x, float y) {
    u64t r; asm("mov.b64 %0, {%1, %2};" : "=l"(r) : "f"(x), "f"(y)); return r;
}
__device__ __forceinline__ u64t pack1(float x) {
    u64t r; asm("mov.b64 %0, {%1, %1};" : "=l"(r) : "f"(x)); return r;
}
__device__ __forceinline__ void ffma2(u64t& d, u64t a, u64t b) {
    asm("fma.rn.f32x2 %0, %1, %2, %0;" : "+l"(d) : "l"(a), "l"(b));
}
__device__ __forceinline__ float2 unpack2(u64t v) {
    float2 f; asm("mov.b64 {%0, %1}, %2;" : "=f"(f.x), "=f"(f.y) : "l"(v)); return f;
}

// ---------------- scratch (device globals) -----------------------------------
__device__ __align__(256) float g_e1[N_NODES * D];
__device__ __align__(256) float g_e2[N_NODES * D];   // also layer-1 input staging
__device__ __align__(256) float g_outI[N_ITEMS * D];
__device__ __align__(256) float g_I[N_ITEMS * D];
__device__ __align__(256) float g_U[BATCH * D];
__device__ int   g_rowptr[N_NODES + 1];
__device__ int   g_wcur[N_NODES];
__device__ int   g_counts[N_NODES];
__device__ int   g_bsum[256];
__device__ __align__(256) int2 g_csr[NNZ];

// ---------------- CSR build ---------------------------------------------------
__global__ void k_zero_counts() {
    int i = blockIdx.x * blockDim.x + threadIdx.x;
    if (i < N_NODES) g_counts[i] = 0;
}

__global__ void k_hist(const int* __restrict__ rows) {
    int i = blockIdx.x * blockDim.x + threadIdx.x;
    if (i < NNZ) atomicAdd(&g_counts[rows[i]], 1);
}

__global__ void k_blockreduce() {
    __shared__ int sh[1024];
    int i = blockIdx.x * 1024 + threadIdx.x;
    sh[threadIdx.x] = (i < N_NODES) ? g_counts[i] : 0;
    __syncthreads();
    for (int s = 512; s > 0; s >>= 1) {
        if (threadIdx.x < s) sh[threadIdx.x] += sh[threadIdx.x + s];
        __syncthreads();
    }
    if (threadIdx.x == 0) g_bsum[blockIdx.x] = sh[0];
}

__global__ void k_blockscan() {
    __shared__ int sh[1024];
    __shared__ int soff;
    int tid = threadIdx.x;
    sh[tid] = (tid < blockIdx.x) ? g_bsum[tid] : 0;
    __syncthreads();
    for (int s = 512; s > 0; s >>= 1) {
        if (tid < s) sh[tid] += sh[tid + s];
        __syncthreads();
    }
    if (tid == 0) soff = sh[0];
    __syncthreads();

    int i = blockIdx.x * 1024 + tid;
    int v = (i < N_NODES) ? g_counts[i] : 0;
    sh[tid] = v;
    __syncthreads();
    for (int off = 1; off < 1024; off <<= 1) {
        int t = (tid >= off) ? sh[tid - off] : 0;
        __syncthreads();
        sh[tid] += t;
        __syncthreads();
    }
    if (i < N_NODES) {
        int excl = sh[tid] - v + soff;
        g_rowptr[i] = excl;
        g_wcur[i]   = excl;
    }
    if (i == 0) g_rowptr[N_NODES] = NNZ;
}

__global__ void k_scatter(const float* __restrict__ vals,
                          const int* __restrict__ rows,
                          const int* __restrict__ cols) {
    int i = blockIdx.x * blockDim.x + threadIdx.x;
    if (i < NNZ) {
        int r = rows[i];
        int pos = atomicAdd(&g_wcur[r], 1);
        g_csr[pos] = make_int2(cols[i], __float_as_int(vals[i]));
    }
}

// ---------------- SPMM over all nodes (contiguous input base) -----------------
__global__ void k_spmm(const float* __restrict__ ein, float* __restrict__ eout) {
    int w    = (blockIdx.x * blockDim.x + threadIdx.x) >> 5;
    int lane = threadIdx.x & 31;
    if (w >= N_NODES) return;
    int s = __ldg(&g_rowptr[w]), e = __ldg(&g_rowptr[w + 1]);
    u64t acc = 0ull;
    int i = s;
    for (; i + 4 <= e; i += 4) {
        int2 c0 = g_csr[i], c1 = g_csr[i + 1], c2 = g_csr[i + 2], c3 = g_csr[i + 3];
        u64t x0 = ((const u64t*)(ein + (size_t)c0.x * D))[lane];
        u64t x1 = ((const u64t*)(ein + (size_t)c1.x * D))[lane];
        u64t x2 = ((const u64t*)(ein + (size_t)c2.x * D))[lane];
        u64t x3 = ((const u64t*)(ein + (size_t)c3.x * D))[lane];
        ffma2(acc, pack1(__int_as_float(c0.y)), x0);
        ffma2(acc, pack1(__int_as_float(c1.y)), x1);
        ffma2(acc, pack1(__int_as_float(c2.y)), x2);
        ffma2(acc, pack1(__int_as_float(c3.y)), x3);
    }
    for (; i < e; i++) {
        int2 c = g_csr[i];
        u64t x = ((const u64t*)(ein + (size_t)c.x * D))[lane];
        ffma2(acc, pack1(__int_as_float(c.y)), x);
    }
    ((float2*)(eout + (size_t)w * D))[lane] = unpack2(acc);
}

// ---------------- layer-3 SPMM: item rows only, fused out epilogue ------------
__global__ void k_spmm_items(const float* __restrict__ item_emb) {
    int w    = (blockIdx.x * blockDim.x + threadIdx.x) >> 5;
    int lane = threadIdx.x & 31;
    if (w >= N_ITEMS) return;
    int node = N_USERS + w;
    int s = __ldg(&g_rowptr[node]), e = __ldg(&g_rowptr[node + 1]);
    u64t acc = 0ull;
    int i = s;
    for (; i + 4 <= e; i += 4) {
        int2 c0 = g_csr[i], c1 = g_csr[i + 1], c2 = g_csr[i + 2], c3 = g_csr[i + 3];
        u64t x0 = ((const u64t*)(g_e2 + (size_t)c0.x * D))[lane];
        u64t x1 = ((const u64t*)(g_e2 + (size_t)c1.x * D))[lane];
        u64t x2 = ((const u64t*)(g_e2 + (size_t)c2.x * D))[lane];
        u64t x3 = ((const u64t*)(g_e2 + (size_t)c3.x * D))[lane];
        ffma2(acc, pack1(__int_as_float(c0.y)), x0);
        ffma2(acc, pack1(__int_as_float(c1.y)), x1);
        ffma2(acc, pack1(__int_as_float(c2.y)), x2);
        ffma2(acc, pack1(__int_as_float(c3.y)), x3);
    }
    for (; i < e; i++) {
        int2 c = g_csr[i];
        u64t x = ((const u64t*)(g_e2 + (size_t)c.x * D))[lane];
        ffma2(acc, pack1(__int_as_float(c.y)), x);
    }
    float2 a = unpack2(acc);
    float2 e0 = ((const float2*)(item_emb + (size_t)w * D))[lane];
    float2 x1 = ((const float2*)(g_e1 + (size_t)node * D))[lane];
    float2 x2 = ((const float2*)(g_e2 + (size_t)node * D))[lane];
    ((float2*)(g_outI + (size_t)w * D))[lane] =
        make_float2(WL * (e0.x + x1.x + x2.x + a.x), WL * (e0.y + x1.y + x2.y + a.y));
}

// ---------------- items: tiled GEMM chain (64 items/block, f32x2) -------------
__global__ __launch_bounds__(256) void k_items(
        const float* __restrict__ pop_emb, const int* __restrict__ bins,
        const float* __restrict__ gW1, const float* __restrict__ gb1,
        const float* __restrict__ gW2, const float* __restrict__ gb2,
        const float* __restrict__ iW1, const float* __restrict__ ib1,
        const float* __restrict__ iW2, const float* __restrict__ ib2) {
    __shared__ float at[64][68];   // A^T  (k, item) ; later Q^T
    __shared__ float xt[64][68];   // P^T  (k, item) ; later F^T
    int tid = threadIdx.x;
    int tx  = tid & 15;            // output-col group
    int ty  = tid >> 4;            // item-row group
    int it0 = blockIdx.x * 64;
    const unsigned FULL = 0xffffffffu;

    // stage A^T and P^T
    for (int idx = tid; idx < 64 * 64; idx += 256) {
        int item = idx >> 6, k = idx & 63;
        int it = it0 + item;
        float a = 0.f; int b = 0;
        if (it < N_ITEMS) { a = g_outI[(size_t)it * D + k]; b = __ldg(&bins[it]); }
        at[k][item] = a;
        xt[k][item] = __ldg(&pop_emb[b * D + k]);
    }
    __syncthreads();

    // GEMM1: H = [A;P] @ gW1   (items 64 x out 64, k = 128)
    u64t h01[4] = {0, 0, 0, 0}, h23[4] = {0, 0, 0, 0};
#pragma unroll 8
    for (int k = 0; k < 64; k++) {
        float4 xa = *(const float4*)&at[k][ty * 4];
        float4 w  = __ldg((const float4*)&gW1[k * 64 + tx * 4]);
        u64t w01 = pack2(w.x, w.y), w23 = pack2(w.z, w.w);
        u64t x0 = pack1(xa.x), x1 = pack1(xa.y), x2 = pack1(xa.z), x3 = pack1(xa.w);
        ffma2(h01[0], x0, w01); ffma2(h23[0], x0, w23);
        ffma2(h01[1], x1, w01); ffma2(h23[1], x1, w23);
        ffma2(h01[2], x2, w01); ffma2(h23[2], x2, w23);
        ffma2(h01[3], x3, w01); ffma2(h23[3], x3, w23);
    }
#pragma unroll 8
    for (int k = 0; k < 64; k++) {
        float4 xa = *(const float4*)&xt[k][ty * 4];
        float4 w  = __ldg((const float4*)&gW1[(64 + k) * 64 + tx * 4]);
        u64t w01 = pack2(w.x, w.y), w23 = pack2(w.z, w.w);
        u64t x0 = pack1(xa.x), x1 = pack1(xa.y), x2 = pack1(xa.z), x3 = pack1(xa.w);
        ffma2(h01[0], x0, w01); ffma2(h23[0], x0, w23);
        ffma2(h01[1], x1, w01); ffma2(h23[1], x1, w23);
        ffma2(h01[2], x2, w01); ffma2(h23[2], x2, w23);
        ffma2(h01[3], x3, w01); ffma2(h23[3], x3, w23);
    }

    // bias + relu + dot(gW2) partial, reduce over the 16 tx lanes
    float4 b1 = __ldg((const float4*)&gb1[tx * 4]);
    float4 w2 = __ldg((const float4*)&gW2[tx * 4]);
    float gb2v = __ldg(gb2);
    float z[4];
#pragma unroll
    for (int r = 0; r < 4; r++) {
        float2 hA = unpack2(h01[r]);
        float2 hB = unpack2(h23[r]);
        float t = fmaxf(hA.x + b1.x, 0.f) * w2.x + fmaxf(hA.y + b1.y, 0.f) * w2.y
                + fmaxf(hB.x + b1.z, 0.f) * w2.z + fmaxf(hB.y + b1.w, 0.f) * w2.w;
#pragma unroll
        for (int off = 8; off > 0; off >>= 1) t += __shfl_xor_sync(FULL, t, off);
        z[r] = 1.f / (1.f + expf(-(t + gb2v)));
    }
    __syncthreads();

    // F^T into xt:  F = (1-z)*A + z*P   (thread handles items ty*4..+3, j = tx*4..+3)
#pragma unroll
    for (int jj = 0; jj < 4; jj++) {
        int j = tx * 4 + jj;
        float4 av = *(const float4*)&at[j][ty * 4];
        float4 pv = *(const float4*)&xt[j][ty * 4];
        float4 f;
        f.x = (1.f - z[0]) * av.x + z[0] * pv.x;
        f.y = (1.f - z[1]) * av.y + z[1] * pv.y;
        f.z = (1.f - z[2]) * av.z + z[2] * pv.z;
        f.w = (1.f - z[3]) * av.w + z[3] * pv.w;
        *(float4*)&xt[j][ty * 4] = f;
    }
    __syncthreads();

    // GEMM2: Q = relu(F @ iW1 + ib1)  -> at (transposed)
    u64t q01[4] = {0, 0, 0, 0}, q23[4] = {0, 0, 0, 0};
#pragma unroll 8
    for (int k = 0; k < 64; k++) {
        float4 xa = *(const float4*)&xt[k][ty * 4];
        float4 w  = __ldg((const float4*)&iW1[k * 64 + tx * 4]);
        u64t w01 = pack2(w.x, w.y), w23 = pack2(w.z, w.w);
        u64t x0 = pack1(xa.x), x1 = pack1(xa.y), x2 = pack1(xa.z), x3 = pack1(xa.w);
        ffma2(q01[0], x0, w01); ffma2(q23[0], x0, w23);
        ffma2(q01[1], x1, w01); ffma2(q23[1], x1, w23);
        ffma2(q01[2], x2, w01); ffma2(q23[2], x2, w23);
        ffma2(q01[3], x3, w01); ffma2(q23[3], x3, w23);
    }
    {
        float4 bi = __ldg((const float4*)&ib1[tx * 4]);
        float qv[4][4];
#pragma unroll
        for (int r = 0; r < 4; r++) {
            float2 qA = unpack2(q01[r]);
            float2 qB = unpack2(q23[r]);
            qv[r][0] = fmaxf(qA.x + bi.x, 0.f);
            qv[r][1] = fmaxf(qA.y + bi.y, 0.f);
            qv[r][2] = fmaxf(qB.x + bi.z, 0.f);
            qv[r][3] = fmaxf(qB.y + bi.w, 0.f);
        }
        __syncthreads();   // everyone done reading at (GEMM1 inputs long gone; safe)
#pragma unroll
        for (int cc = 0; cc < 4; cc++)
            *(float4*)&at[tx * 4 + cc][ty * 4] =
                make_float4(qv[0][cc], qv[1][cc], qv[2][cc], qv[3][cc]);
    }
    __syncthreads();

    // GEMM3: Y = Q @ iW2 + ib2 -> g_I
    u64t y01[4] = {0, 0, 0, 0}, y23[4] = {0, 0, 0, 0};
#pragma unroll 8
    for (int k = 0; k < 64; k++) {
        float4 xa = *(const float4*)&at[k][ty * 4];
        float4 w  = __ldg((const float4*)&iW2[k * 64 + tx * 4]);
        u64t w01 = pack2(w.x, w.y), w23 = pack2(w.z, w.w);
        u64t x0 = pack1(xa.x), x1 = pack1(xa.y), x2 = pack1(xa.z), x3 = pack1(xa.w);
        ffma2(y01[0], x0, w01); ffma2(y23[0], x0, w23);
        ffma2(y01[1], x1, w01); ffma2(y23[1], x1, w23);
        ffma2(y01[2], x2, w01); ffma2(y23[2], x2, w23);
        ffma2(y01[3], x3, w01); ffma2(y23[3], x3, w23);
    }
    float4 bo = __ldg((const float4*)&ib2[tx * 4]);
#pragma unroll
    for (int r = 0; r < 4; r++) {
        int item = it0 + ty * 4 + r;
        if (item < N_ITEMS) {
            float2 yA = unpack2(y01[r]);
            float2 yB = unpack2(y23[r]);
            *(float4*)&g_I[(size_t)item * D + tx * 4] =
                make_float4(yA.x + bo.x, yA.y + bo.y, yB.x + bo.z, yB.y + bo.w);
        }
    }
}

// ---------------- users: e3 row + out + MLP (warp per user) -------------------
__global__ void k_users(const int* __restrict__ users, const float* __restrict__ user_emb,
                        const float* __restrict__ uW1, const float* __restrict__ ub1,
                        const float* __restrict__ uW2, const float* __restrict__ ub2) {
    int w    = (blockIdx.x * blockDim.x + threadIdx.x) >> 5;
    int lane = threadIdx.x & 31;
    if (w >= BATCH) return;
    const unsigned FULL = 0xffffffffu;
    int u = __ldg(&users[w]);
    int s = __ldg(&g_rowptr[u]), e = __ldg(&g_rowptr[u + 1]);
    float ax = 0.f, ay = 0.f;
    for (int i = s; i < e; i++) {
        int2 c = g_csr[i];
        float2 x = ((const float2*)(g_e2 + (size_t)c.x * D))[lane];
        float v = __int_as_float(c.y);
        ax += v * x.x; ay += v * x.y;
    }
    float2 e0 = ((const float2*)(user_emb + (size_t)u * D))[lane];
    float2 x1 = ((const float2*)(g_e1 + (size_t)u * D))[lane];
    float2 x2 = ((const float2*)(g_e2 + (size_t)u * D))[lane];
    float xx = WL * (e0.x + x1.x + x2.x + ax);
    float xy = WL * (e0.y + x1.y + x2.y + ay);

    const float2* W1 = (const float2*)uW1;
    float hx = 0.f, hy = 0.f;
#pragma unroll 8
    for (int m = 0; m < 32; m++) {
        float2 wA = W1[(2 * m) * 32 + lane];
        float2 wB = W1[(2 * m + 1) * 32 + lane];
        float xA = __shfl_sync(FULL, xx, m);
        float xB = __shfl_sync(FULL, xy, m);
        hx += xA * wA.x + xB * wB.x;
        hy += xA * wA.y + xB * wB.y;
    }
    float2 b1 = ((const float2*)ub1)[lane];
    hx = fmaxf(hx + b1.x, 0.f);
    hy = fmaxf(hy + b1.y, 0.f);

    const float2* W2 = (const float2*)uW2;
    float yx = 0.f, yy = 0.f;
#pragma unroll 8
    for (int m = 0; m < 32; m++) {
        float2 wA = W2[(2 * m) * 32 + lane];
        float2 wB = W2[(2 * m + 1) * 32 + lane];
        float xA = __shfl_sync(FULL, hx, m);
        float xB = __shfl_sync(FULL, hy, m);
        yx += xA * wA.x + xB * wB.x;
        yy += xA * wA.y + xB * wB.y;
    }
    float2 b2 = ((const float2*)ub2)[lane];
    ((float2*)(g_U + (size_t)w * D))[lane] = make_float2(yx + b2.x, yy + b2.y);
}

// ---------------- scores: [256,64] @ [50000,64]^T + biases (f32x2) ------------
__global__ __launch_bounds__(256) void k_scores(
        const float* __restrict__ user_bias,
        const float* __restrict__ item_bias,
        const int* __restrict__ users,
        float* __restrict__ out) {
    __shared__ float UsT[64][68];   // (k, user)
    __shared__ float IsT[64][68];   // (k, item)
    int tid = threadIdx.x;
    int tx = tid & 15;              // item dir
    int ty = tid >> 4;              // user dir
    int m0 = blockIdx.y * 64;
    int n0 = blockIdx.x * 64;

    for (int idx = tid; idx < 64 * 64; idx += 256) {
        int row = idx >> 6, k = idx & 63;
        UsT[k][row] = g_U[(size_t)(m0 + row) * D + k];
        int n = n0 + row;
        IsT[k][row] = (n < N_ITEMS) ? g_I[(size_t)n * D + k] : 0.f;
    }
    __syncthreads();

    u64t a01[4] = {0, 0, 0, 0}, a23[4] = {0, 0, 0, 0};
#pragma unroll 8
    for (int k = 0; k < 64; k++) {
        float4 uu = *(const float4*)&UsT[k][ty * 4];
        float4 vv = *(const float4*)&IsT[k][tx * 4];
        u64t v01 = pack2(vv.x, vv.y), v23 = pack2(vv.z, vv.w);
        u64t u0 = pack1(uu.x), u1 = pack1(uu.y), u2 = pack1(uu.z), u3 = pack1(uu.w);
        ffma2(a01[0], u0, v01); ffma2(a23[0], u0, v23);
        ffma2(a01[1], u1, v01); ffma2(a23[1], u1, v23);
        ffma2(a01[2], u2, v01); ffma2(a23[2], u2, v23);
        ffma2(a01[3], u3, v01); ffma2(a23[3], u3, v23);
    }

    int n = n0 + tx * 4;
    if (n < N_ITEMS) {
        float4 ibv = *(const float4*)&item_bias[n];
#pragma unroll
        for (int r = 0; r < 4; r++) {
            int m = m0 + ty * 4 + r;
            float ub = __ldg(&user_bias[__ldg(&users[m])]);
            float2 sA = unpack2(a01[r]);
            float2 sB = unpack2(a23[r]);
            *(float4*)&out[(size_t)m * N_ITEMS + n] =
                make_float4(sA.x + ub + ibv.x, sA.y + ub + ibv.y,
                            sB.x + ub + ibv.z, sB.y + ub + ibv.w);
        }
    }
}

// ---------------- launch -------------------------------------------------------
extern "C" void kernel_launch(void* const* d_in, const int* in_sizes, int n_in,
                              void* d_out, int out_size) {
    const float* user_emb  = (const float*)d_in[0];
    const float* item_emb  = (const float*)d_in[1];
    const float* user_bias = (const float*)d_in[2];
    const float* item_bias = (const float*)d_in[3];
    const float* pop_emb   = (const float*)d_in[4];
    const float* uW1 = (const float*)d_in[5];
    const float* ub1 = (const float*)d_in[6];
    const float* uW2 = (const float*)d_in[7];
    const float* ub2 = (const float*)d_in[8];
    const float* iW1 = (const float*)d_in[9];
    const float* ib1 = (const float*)d_in[10];
    const float* iW2 = (const float*)d_in[11];
    const float* ib2 = (const float*)d_in[12];
    const float* gW1 = (const float*)d_in[13];
    const float* gb1 = (const float*)d_in[14];
    const float* gW2 = (const float*)d_in[15];
    const float* gb2 = (const float*)d_in[16];
    const float* adj_vals = (const float*)d_in[17];
    const int*   adj_rows = (const int*)d_in[18];
    const int*   adj_cols = (const int*)d_in[19];
    const int*   bins     = (const int*)d_in[20];
    const int*   users    = (const int*)d_in[21];
    float* out = (float*)d_out;

    float* e1; cudaGetSymbolAddress((void**)&e1, g_e1);
    float* e2; cudaGetSymbolAddress((void**)&e2, g_e2);

    // stage concatenated embedding into e2 (layer-1 input)
    cudaMemcpyAsync(e2, user_emb, (size_t)N_USERS * D * sizeof(float),
                    cudaMemcpyDeviceToDevice);
    cudaMemcpyAsync(e2 + (size_t)N_USERS * D, item_emb,
                    (size_t)N_ITEMS * D * sizeof(float), cudaMemcpyDeviceToDevice);

    // CSR build
    k_zero_counts<<<(N_NODES + 255) / 256, 256>>>();
    k_hist<<<(NNZ + 255) / 256, 256>>>(adj_rows);
    int nb = (N_NODES + 1023) / 1024;
    k_blockreduce<<<nb, 1024>>>();
    k_blockscan<<<nb, 1024>>>();
    k_scatter<<<(NNZ + 255) / 256, 256>>>(adj_vals, adj_rows, adj_cols);

    int fullBlocks = (N_NODES * 32 + 255) / 256;
    k_spmm<<<fullBlocks, 256>>>(e2, e1);          // layer 1: e2(staged emb) -> e1
    k_spmm<<<fullBlocks, 256>>>(e1, e2);          // layer 2: e1 -> e2
    int itemBlocks = (N_ITEMS * 32 + 255) / 256;
    k_spmm_items<<<itemBlocks, 256>>>(item_emb);  // layer 3 (items) + out epilogue

    k_items<<<(N_ITEMS + 63) / 64, 256>>>(pop_emb, bins, gW1, gb1, gW2, gb2,
                                          iW1, ib1, iW2, ib2);
    k_users<<<(BATCH * 32 + 255) / 256, 256>>>(users, user_emb, uW1, ub1, uW2, ub2);

    dim3 grid((N_ITEMS + 63) / 64, BATCH / 64);
    k_scores<<<grid, 256>>>(user_bias, item_bias, users, out);
}

// round 4
// speedup vs baseline: 1.4125x; 1.0608x over previous
#include <cuda_runtime.h>
#include <math.h>

#define N_USERS 100000
#define N_ITEMS 50000
#define N_NODES 150000
#define D       64
#define NNZ     2000000
#define BATCH   256
#define WL      0.25f   // 1/(N_LAYERS+1)

typedef unsigned long long u64t;
#define FULL 0xffffffffu

// ---------------- f32x2 packed-FMA helpers (sm_100+) -------------------------
__device__ __forceinline__ u64t pack2(float x, float y) {
    u64t r; asm("mov.b64 %0, {%1, %2};" : "=l"(r) : "f"(x), "f"(y)); return r;
}
__device__ __forceinline__ u64t pack1(float x) {
    u64t r; asm("mov.b64 %0, {%1, %1};" : "=l"(r) : "f"(x)); return r;
}
__device__ __forceinline__ void ffma2(u64t& d, u64t a, u64t b) {
    asm("fma.rn.f32x2 %0, %1, %2, %0;" : "+l"(d) : "l"(a), "l"(b));
}
__device__ __forceinline__ float2 unpack2(u64t v) {
    float2 f; asm("mov.b64 {%0, %1}, %2;" : "=f"(f.x), "=f"(f.y) : "l"(v)); return f;
}

// ---------------- scratch (device globals) -----------------------------------
__device__ __align__(256) float g_e1[N_NODES * D];
__device__ __align__(256) float g_e2[N_NODES * D];   // also layer-1 input staging
__device__ __align__(256) float g_outI[N_ITEMS * D];
__device__ __align__(256) float g_I[N_ITEMS * D];
__device__ __align__(256) float g_U[BATCH * D];
__device__ int   g_rowptr[N_NODES + 1];
__device__ int   g_wcur[N_NODES];
__device__ int   g_counts[N_NODES];
__device__ int   g_bsum[256];
__device__ __align__(256) int2 g_csr[NNZ];

// ---------------- init: zero counts + stage concat embedding into g_e2 --------
__global__ void k_init(const float* __restrict__ ue, const float* __restrict__ ie) {
    int t = blockIdx.x * blockDim.x + threadIdx.x;   // float4 index
    const int NU4 = N_USERS * D / 4;
    const int NT4 = N_NODES * D / 4;
    if (t < NT4) {
        float4 v = (t < NU4) ? ((const float4*)ue)[t] : ((const float4*)ie)[t - NU4];
        ((float4*)g_e2)[t] = v;
    }
    if (t < N_NODES) g_counts[t] = 0;
}

// ---------------- CSR build ---------------------------------------------------
__global__ void k_hist(const int* __restrict__ rows) {
    int i = blockIdx.x * blockDim.x + threadIdx.x;
    if (i < NNZ) atomicAdd(&g_counts[rows[i]], 1);
}

__global__ void k_blockreduce() {
    __shared__ int wsum[32];
    int i = blockIdx.x * 1024 + threadIdx.x;
    int v = (i < N_NODES) ? g_counts[i] : 0;
#pragma unroll
    for (int off = 16; off > 0; off >>= 1) v += __shfl_down_sync(FULL, v, off);
    int wid = threadIdx.x >> 5, lane = threadIdx.x & 31;
    if (lane == 0) wsum[wid] = v;
    __syncthreads();
    if (wid == 0) {
        int s = wsum[lane];
#pragma unroll
        for (int off = 16; off > 0; off >>= 1) s += __shfl_down_sync(FULL, s, off);
        if (lane == 0) g_bsum[blockIdx.x] = s;
    }
}

__global__ void k_blockscan() {
    __shared__ int wsum[33];
    __shared__ int soff_sh;
    int tid = threadIdx.x;
    int wid = tid >> 5, lane = tid & 31;

    // prefix of block sums [0, blockIdx.x) — 147 values, 256 threads cover it
    {
        int p = (tid < blockIdx.x && tid < 256) ? g_bsum[tid] : 0;
        if (tid < 256) {
#pragma unroll
            for (int off = 16; off > 0; off >>= 1) p += __shfl_down_sync(FULL, p, off);
            if (lane == 0) wsum[wid] = p;
        }
        __syncthreads();
        if (tid < 8) {
            int s = wsum[tid];
#pragma unroll
            for (int off = 4; off > 0; off >>= 1) s += __shfl_down_sync(0xffu, s, off);
            if (tid == 0) soff_sh = s;
        }
        __syncthreads();
    }

    int i = blockIdx.x * 1024 + tid;
    int v = (i < N_NODES) ? g_counts[i] : 0;
    // warp inclusive scan
    int sc = v;
#pragma unroll
    for (int off = 1; off < 32; off <<= 1) {
        int t = __shfl_up_sync(FULL, sc, off);
        if (lane >= off) sc += t;
    }
    if (lane == 31) wsum[wid] = sc;
    __syncthreads();
    if (wid == 0) {
        int s = (lane < 32) ? wsum[lane] : 0;
#pragma unroll
        for (int off = 1; off < 32; off <<= 1) {
            int t = __shfl_up_sync(FULL, s, off);
            if (lane >= off) s += t;
        }
        wsum[lane + 1] = s;   // exclusive for warp w stored at wsum[w+1]... see below
        if (lane == 0) wsum[0] = 0;
    }
    __syncthreads();
    // wsum[wid] = sum of warps [0, wid)
    if (i < N_NODES) {
        int excl = sc - v + wsum[wid] + soff_sh;
        g_rowptr[i] = excl;
        g_wcur[i]   = excl;
    }
    if (i == 0) g_rowptr[N_NODES] = NNZ;
}

__global__ void k_scatter(const float* __restrict__ vals,
                          const int* __restrict__ rows,
                          const int* __restrict__ cols) {
    int i = blockIdx.x * blockDim.x + threadIdx.x;
    if (i < NNZ) {
        int r = rows[i];
        int pos = atomicAdd(&g_wcur[r], 1);
        g_csr[pos] = make_int2(cols[i], __float_as_int(vals[i]));
    }
}

// ---------------- SPMM: half-warp per edge stream, float4 gathers -------------
__global__ void k_spmm(const float* __restrict__ ein, float* __restrict__ eout) {
    int w    = (blockIdx.x * blockDim.x + threadIdx.x) >> 5;
    int lane = threadIdx.x & 31;
    if (w >= N_NODES) return;
    int half = lane >> 4;          // 0 or 1
    int j    = lane & 15;          // float4 slot within row
    int s = __ldg(&g_rowptr[w]), e = __ldg(&g_rowptr[w + 1]);

    u64t a01 = 0ull, a23 = 0ull;   // float4 accumulator
    int i = s + half;
    for (; i + 6 < e; i += 8) {
        int2 c0 = __ldg(&g_csr[i]);
        int2 c1 = __ldg(&g_csr[i + 2]);
        int2 c2 = __ldg(&g_csr[i + 4]);
        int2 c3 = __ldg(&g_csr[i + 6]);
        float4 x0 = __ldg((const float4*)(ein + (size_t)c0.x * D) + j);
        float4 x1 = __ldg((const float4*)(ein + (size_t)c1.x * D) + j);
        float4 x2 = __ldg((const float4*)(ein + (size_t)c2.x * D) + j);
        float4 x3 = __ldg((const float4*)(ein + (size_t)c3.x * D) + j);
        u64t v0 = pack1(__int_as_float(c0.y)), v1 = pack1(__int_as_float(c1.y));
        u64t v2 = pack1(__int_as_float(c2.y)), v3 = pack1(__int_as_float(c3.y));
        ffma2(a01, v0, pack2(x0.x, x0.y)); ffma2(a23, v0, pack2(x0.z, x0.w));
        ffma2(a01, v1, pack2(x1.x, x1.y)); ffma2(a23, v1, pack2(x1.z, x1.w));
        ffma2(a01, v2, pack2(x2.x, x2.y)); ffma2(a23, v2, pack2(x2.z, x2.w));
        ffma2(a01, v3, pack2(x3.x, x3.y)); ffma2(a23, v3, pack2(x3.z, x3.w));
    }
    for (; i < e; i += 2) {
        int2 c = __ldg(&g_csr[i]);
        float4 x = __ldg((const float4*)(ein + (size_t)c.x * D) + j);
        u64t v = pack1(__int_as_float(c.y));
        ffma2(a01, v, pack2(x.x, x.y)); ffma2(a23, v, pack2(x.z, x.w));
    }
    float2 lo = unpack2(a01), hi = unpack2(a23);
    float4 a = make_float4(lo.x, lo.y, hi.x, hi.y);
    a.x += __shfl_down_sync(FULL, a.x, 16);
    a.y += __shfl_down_sync(FULL, a.y, 16);
    a.z += __shfl_down_sync(FULL, a.z, 16);
    a.w += __shfl_down_sync(FULL, a.w, 16);
    if (half == 0)
        ((float4*)(eout + (size_t)w * D))[j] = a;
}

// ---------------- layer-3 SPMM: item rows only, fused out epilogue ------------
__global__ void k_spmm_items(const float* __restrict__ item_emb) {
    int w    = (blockIdx.x * blockDim.x + threadIdx.x) >> 5;
    int lane = threadIdx.x & 31;
    if (w >= N_ITEMS) return;
    int half = lane >> 4;
    int j    = lane & 15;
    int node = N_USERS + w;
    int s = __ldg(&g_rowptr[node]), e = __ldg(&g_rowptr[node + 1]);

    u64t a01 = 0ull, a23 = 0ull;
    int i = s + half;
    for (; i + 6 < e; i += 8) {
        int2 c0 = __ldg(&g_csr[i]);
        int2 c1 = __ldg(&g_csr[i + 2]);
        int2 c2 = __ldg(&g_csr[i + 4]);
        int2 c3 = __ldg(&g_csr[i + 6]);
        float4 x0 = __ldg((const float4*)(g_e2 + (size_t)c0.x * D) + j);
        float4 x1 = __ldg((const float4*)(g_e2 + (size_t)c1.x * D) + j);
        float4 x2 = __ldg((const float4*)(g_e2 + (size_t)c2.x * D) + j);
        float4 x3 = __ldg((const float4*)(g_e2 + (size_t)c3.x * D) + j);
        u64t v0 = pack1(__int_as_float(c0.y)), v1 = pack1(__int_as_float(c1.y));
        u64t v2 = pack1(__int_as_float(c2.y)), v3 = pack1(__int_as_float(c3.y));
        ffma2(a01, v0, pack2(x0.x, x0.y)); ffma2(a23, v0, pack2(x0.z, x0.w));
        ffma2(a01, v1, pack2(x1.x, x1.y)); ffma2(a23, v1, pack2(x1.z, x1.w));
        ffma2(a01, v2, pack2(x2.x, x2.y)); ffma2(a23, v2, pack2(x2.z, x2.w));
        ffma2(a01, v3, pack2(x3.x, x3.y)); ffma2(a23, v3, pack2(x3.z, x3.w));
    }
    for (; i < e; i += 2) {
        int2 c = __ldg(&g_csr[i]);
        float4 x = __ldg((const float4*)(g_e2 + (size_t)c.x * D) + j);
        u64t v = pack1(__int_as_float(c.y));
        ffma2(a01, v, pack2(x.x, x.y)); ffma2(a23, v, pack2(x.z, x.w));
    }
    float2 lo = unpack2(a01), hi = unpack2(a23);
    float4 a = make_float4(lo.x, lo.y, hi.x, hi.y);
    a.x += __shfl_down_sync(FULL, a.x, 16);
    a.y += __shfl_down_sync(FULL, a.y, 16);
    a.z += __shfl_down_sync(FULL, a.z, 16);
    a.w += __shfl_down_sync(FULL, a.w, 16);
    if (half == 0) {
        float4 e0 = __ldg((const float4*)(item_emb + (size_t)w * D) + j);
        float4 x1 = *((const float4*)(g_e1 + (size_t)node * D) + j);
        float4 x2 = *((const float4*)(g_e2 + (size_t)node * D) + j);
        ((float4*)(g_outI + (size_t)w * D))[j] = make_float4(
            WL * (e0.x + x1.x + x2.x + a.x), WL * (e0.y + x1.y + x2.y + a.y),
            WL * (e0.z + x1.z + x2.z + a.z), WL * (e0.w + x1.w + x2.w + a.w));
    }
}

// ---------------- items: tiled GEMM chain (64 items/block, f32x2) -------------
__global__ __launch_bounds__(256) void k_items(
        const float* __restrict__ pop_emb, const int* __restrict__ bins,
        const float* __restrict__ gW1, const float* __restrict__ gb1,
        const float* __restrict__ gW2, const float* __restrict__ gb2,
        const float* __restrict__ iW1, const float* __restrict__ ib1,
        const float* __restrict__ iW2, const float* __restrict__ ib2) {
    __shared__ float at[64][68];   // A^T  (k, item) ; later Q^T
    __shared__ float xt[64][68];   // P^T  (k, item) ; later F^T
    int tid = threadIdx.x;
    int tx  = tid & 15;            // output-col group
    int ty  = tid >> 4;            // item-row group
    int it0 = blockIdx.x * 64;

    for (int idx = tid; idx < 64 * 64; idx += 256) {
        int item = idx >> 6, k = idx & 63;
        int it = it0 + item;
        float a = 0.f; int b = 0;
        if (it < N_ITEMS) { a = g_outI[(size_t)it * D + k]; b = __ldg(&bins[it]); }
        at[k][item] = a;
        xt[k][item] = __ldg(&pop_emb[b * D + k]);
    }
    __syncthreads();

    u64t h01[4] = {0, 0, 0, 0}, h23[4] = {0, 0, 0, 0};
#pragma unroll 8
    for (int k = 0; k < 64; k++) {
        float4 xa = *(const float4*)&at[k][ty * 4];
        float4 w  = __ldg((const float4*)&gW1[k * 64 + tx * 4]);
        u64t w01 = pack2(w.x, w.y), w23 = pack2(w.z, w.w);
        u64t x0 = pack1(xa.x), x1 = pack1(xa.y), x2 = pack1(xa.z), x3 = pack1(xa.w);
        ffma2(h01[0], x0, w01); ffma2(h23[0], x0, w23);
        ffma2(h01[1], x1, w01); ffma2(h23[1], x1, w23);
        ffma2(h01[2], x2, w01); ffma2(h23[2], x2, w23);
        ffma2(h01[3], x3, w01); ffma2(h23[3], x3, w23);
    }
#pragma unroll 8
    for (int k = 0; k < 64; k++) {
        float4 xa = *(const float4*)&xt[k][ty * 4];
        float4 w  = __ldg((const float4*)&gW1[(64 + k) * 64 + tx * 4]);
        u64t w01 = pack2(w.x, w.y), w23 = pack2(w.z, w.w);
        u64t x0 = pack1(xa.x), x1 = pack1(xa.y), x2 = pack1(xa.z), x3 = pack1(xa.w);
        ffma2(h01[0], x0, w01); ffma2(h23[0], x0, w23);
        ffma2(h01[1], x1, w01); ffma2(h23[1], x1, w23);
        ffma2(h01[2], x2, w01); ffma2(h23[2], x2, w23);
        ffma2(h01[3], x3, w01); ffma2(h23[3], x3, w23);
    }

    float4 b1 = __ldg((const float4*)&gb1[tx * 4]);
    float4 w2 = __ldg((const float4*)&gW2[tx * 4]);
    float gb2v = __ldg(gb2);
    float z[4];
#pragma unroll
    for (int r = 0; r < 4; r++) {
        float2 hA = unpack2(h01[r]);
        float2 hB = unpack2(h23[r]);
        float t = fmaxf(hA.x + b1.x, 0.f) * w2.x + fmaxf(hA.y + b1.y, 0.f) * w2.y
                + fmaxf(hB.x + b1.z, 0.f) * w2.z + fmaxf(hB.y + b1.w, 0.f) * w2.w;
#pragma unroll
        for (int off = 8; off > 0; off >>= 1) t += __shfl_xor_sync(FULL, t, off);
        z[r] = 1.f / (1.f + expf(-(t + gb2v)));
    }
    __syncthreads();

#pragma unroll
    for (int jj = 0; jj < 4; jj++) {
        int j = tx * 4 + jj;
        float4 av = *(const float4*)&at[j][ty * 4];
        float4 pv = *(const float4*)&xt[j][ty * 4];
        float4 f;
        f.x = (1.f - z[0]) * av.x + z[0] * pv.x;
        f.y = (1.f - z[1]) * av.y + z[1] * pv.y;
        f.z = (1.f - z[2]) * av.z + z[2] * pv.z;
        f.w = (1.f - z[3]) * av.w + z[3] * pv.w;
        *(float4*)&xt[j][ty * 4] = f;
    }
    __syncthreads();

    u64t q01[4] = {0, 0, 0, 0}, q23[4] = {0, 0, 0, 0};
#pragma unroll 8
    for (int k = 0; k < 64; k++) {
        float4 xa = *(const float4*)&xt[k][ty * 4];
        float4 w  = __ldg((const float4*)&iW1[k * 64 + tx * 4]);
        u64t w01 = pack2(w.x, w.y), w23 = pack2(w.z, w.w);
        u64t x0 = pack1(xa.x), x1 = pack1(xa.y), x2 = pack1(xa.z), x3 = pack1(xa.w);
        ffma2(q01[0], x0, w01); ffma2(q23[0], x0, w23);
        ffma2(q01[1], x1, w01); ffma2(q23[1], x1, w23);
        ffma2(q01[2], x2, w01); ffma2(q23[2], x2, w23);
        ffma2(q01[3], x3, w01); ffma2(q23[3], x3, w23);
    }
    {
        float4 bi = __ldg((const float4*)&ib1[tx * 4]);
        float qv[4][4];
#pragma unroll
        for (int r = 0; r < 4; r++) {
            float2 qA = unpack2(q01[r]);
            float2 qB = unpack2(q23[r]);
            qv[r][0] = fmaxf(qA.x + bi.x, 0.f);
            qv[r][1] = fmaxf(qA.y + bi.y, 0.f);
            qv[r][2] = fmaxf(qB.x + bi.z, 0.f);
            qv[r][3] = fmaxf(qB.y + bi.w, 0.f);
        }
        __syncthreads();
#pragma unroll
        for (int cc = 0; cc < 4; cc++)
            *(float4*)&at[tx * 4 + cc][ty * 4] =
                make_float4(qv[0][cc], qv[1][cc], qv[2][cc], qv[3][cc]);
    }
    __syncthreads();

    u64t y01[4] = {0, 0, 0, 0}, y23[4] = {0, 0, 0, 0};
#pragma unroll 8
    for (int k = 0; k < 64; k++) {
        float4 xa = *(const float4*)&at[k][ty * 4];
        float4 w  = __ldg((const float4*)&iW2[k * 64 + tx * 4]);
        u64t w01 = pack2(w.x, w.y), w23 = pack2(w.z, w.w);
        u64t x0 = pack1(xa.x), x1 = pack1(xa.y), x2 = pack1(xa.z), x3 = pack1(xa.w);
        ffma2(y01[0], x0, w01); ffma2(y23[0], x0, w23);
        ffma2(y01[1], x1, w01); ffma2(y23[1], x1, w23);
        ffma2(y01[2], x2, w01); ffma2(y23[2], x2, w23);
        ffma2(y01[3], x3, w01); ffma2(y23[3], x3, w23);
    }
    float4 bo = __ldg((const float4*)&ib2[tx * 4]);
#pragma unroll
    for (int r = 0; r < 4; r++) {
        int item = it0 + ty * 4 + r;
        if (item < N_ITEMS) {
            float2 yA = unpack2(y01[r]);
            float2 yB = unpack2(y23[r]);
            *(float4*)&g_I[(size_t)item * D + tx * 4] =
                make_float4(yA.x + bo.x, yA.y + bo.y, yB.x + bo.z, yB.y + bo.w);
        }
    }
}

// ---------------- users: e3 row + out + MLP (warp per user) -------------------
__global__ void k_users(const int* __restrict__ users, const float* __restrict__ user_emb,
                        const float* __restrict__ uW1, const float* __restrict__ ub1,
                        const float* __restrict__ uW2, const float* __restrict__ ub2) {
    int w    = (blockIdx.x * blockDim.x + threadIdx.x) >> 5;
    int lane = threadIdx.x & 31;
    if (w >= BATCH) return;
    int u = __ldg(&users[w]);
    int s = __ldg(&g_rowptr[u]), e = __ldg(&g_rowptr[u + 1]);
    float ax = 0.f, ay = 0.f;
    for (int i = s; i < e; i++) {
        int2 c = __ldg(&g_csr[i]);
        float2 x = ((const float2*)(g_e2 + (size_t)c.x * D))[lane];
        float v = __int_as_float(c.y);
        ax += v * x.x; ay += v * x.y;
    }
    float2 e0 = ((const float2*)(user_emb + (size_t)u * D))[lane];
    float2 x1 = ((const float2*)(g_e1 + (size_t)u * D))[lane];
    float2 x2 = ((const float2*)(g_e2 + (size_t)u * D))[lane];
    float xx = WL * (e0.x + x1.x + x2.x + ax);
    float xy = WL * (e0.y + x1.y + x2.y + ay);

    const float2* W1 = (const float2*)uW1;
    float hx = 0.f, hy = 0.f;
#pragma unroll 8
    for (int m = 0; m < 32; m++) {
        float2 wA = W1[(2 * m) * 32 + lane];
        float2 wB = W1[(2 * m + 1) * 32 + lane];
        float xA = __shfl_sync(FULL, xx, m);
        float xB = __shfl_sync(FULL, xy, m);
        hx += xA * wA.x + xB * wB.x;
        hy += xA * wA.y + xB * wB.y;
    }
    float2 b1 = ((const float2*)ub1)[lane];
    hx = fmaxf(hx + b1.x, 0.f);
    hy = fmaxf(hy + b1.y, 0.f);

    const float2* W2 = (const float2*)uW2;
    float yx = 0.f, yy = 0.f;
#pragma unroll 8
    for (int m = 0; m < 32; m++) {
        float2 wA = W2[(2 * m) * 32 + lane];
        float2 wB = W2[(2 * m + 1) * 32 + lane];
        float xA = __shfl_sync(FULL, hx, m);
        float xB = __shfl_sync(FULL, hy, m);
        yx += xA * wA.x + xB * wB.x;
        yy += xA * wA.y + xB * wB.y;
    }
    float2 b2 = ((const float2*)ub2)[lane];
    ((float2*)(g_U + (size_t)w * D))[lane] = make_float2(yx + b2.x, yy + b2.y);
}

// ---------------- scores: [256,64] @ [50000,64]^T + biases (f32x2) ------------
__global__ __launch_bounds__(256) void k_scores(
        const float* __restrict__ user_bias,
        const float* __restrict__ item_bias,
        const int* __restrict__ users,
        float* __restrict__ out) {
    __shared__ float UsT[64][68];
    __shared__ float IsT[64][68];
    int tid = threadIdx.x;
    int tx = tid & 15;
    int ty = tid >> 4;
    int m0 = blockIdx.y * 64;
    int n0 = blockIdx.x * 64;

    for (int idx = tid; idx < 64 * 64; idx += 256) {
        int row = idx >> 6, k = idx & 63;
        UsT[k][row] = g_U[(size_t)(m0 + row) * D + k];
        int n = n0 + row;
        IsT[k][row] = (n < N_ITEMS) ? g_I[(size_t)n * D + k] : 0.f;
    }
    __syncthreads();

    u64t a01[4] = {0, 0, 0, 0}, a23[4] = {0, 0, 0, 0};
#pragma unroll 8
    for (int k = 0; k < 64; k++) {
        float4 uu = *(const float4*)&UsT[k][ty * 4];
        float4 vv = *(const float4*)&IsT[k][tx * 4];
        u64t v01 = pack2(vv.x, vv.y), v23 = pack2(vv.z, vv.w);
        u64t u0 = pack1(uu.x), u1 = pack1(uu.y), u2 = pack1(uu.z), u3 = pack1(uu.w);
        ffma2(a01[0], u0, v01); ffma2(a23[0], u0, v23);
        ffma2(a01[1], u1, v01); ffma2(a23[1], u1, v23);
        ffma2(a01[2], u2, v01); ffma2(a23[2], u2, v23);
        ffma2(a01[3], u3, v01); ffma2(a23[3], u3, v23);
    }

    int n = n0 + tx * 4;
    if (n < N_ITEMS) {
        float4 ibv = *(const float4*)&item_bias[n];
#pragma unroll
        for (int r = 0; r < 4; r++) {
            int m = m0 + ty * 4 + r;
            float ub = __ldg(&user_bias[__ldg(&users[m])]);
            float2 sA = unpack2(a01[r]);
            float2 sB = unpack2(a23[r]);
            *(float4*)&out[(size_t)m * N_ITEMS + n] =
                make_float4(sA.x + ub + ibv.x, sA.y + ub + ibv.y,
                            sB.x + ub + ibv.z, sB.y + ub + ibv.w);
        }
    }
}

// ---------------- launch -------------------------------------------------------
extern "C" void kernel_launch(void* const* d_in, const int* in_sizes, int n_in,
                              void* d_out, int out_size) {
    const float* user_emb  = (const float*)d_in[0];
    const float* item_emb  = (const float*)d_in[1];
    const float* user_bias = (const float*)d_in[2];
    const float* item_bias = (const float*)d_in[3];
    const float* pop_emb   = (const float*)d_in[4];
    const float* uW1 = (const float*)d_in[5];
    const float* ub1 = (const float*)d_in[6];
    const float* uW2 = (const float*)d_in[7];
    const float* ub2 = (const float*)d_in[8];
    const float* iW1 = (const float*)d_in[9];
    const float* ib1 = (const float*)d_in[10];
    const float* iW2 = (const float*)d_in[11];
    const float* ib2 = (const float*)d_in[12];
    const float* gW1 = (const float*)d_in[13];
    const float* gb1 = (const float*)d_in[14];
    const float* gW2 = (const float*)d_in[15];
    const float* gb2 = (const float*)d_in[16];
    const float* adj_vals = (const float*)d_in[17];
    const int*   adj_rows = (const int*)d_in[18];
    const int*   adj_cols = (const int*)d_in[19];
    const int*   bins     = (const int*)d_in[20];
    const int*   users    = (const int*)d_in[21];
    float* out = (float*)d_out;

    float* e1; cudaGetSymbolAddress((void**)&e1, g_e1);
    float* e2; cudaGetSymbolAddress((void**)&e2, g_e2);

    // 1: init (zero counts + stage embeddings into e2)
    k_init<<<(N_NODES * D / 4 + 255) / 256, 256>>>(user_emb, item_emb);
    // 2-5: CSR build
    k_hist<<<(NNZ + 255) / 256, 256>>>(adj_rows);
    int nb = (N_NODES + 1023) / 1024;
    k_blockreduce<<<nb, 1024>>>();
    k_blockscan<<<nb, 1024>>>();
    k_scatter<<<(NNZ + 255) / 256, 256>>>(adj_vals, adj_rows, adj_cols);

    // 6: layer 1 (PROFILED by ncu -s 5 -c 1)
    int fullBlocks = (N_NODES * 32 + 255) / 256;
    k_spmm<<<fullBlocks, 256>>>(e2, e1);
    // 7: layer 2
    k_spmm<<<fullBlocks, 256>>>(e1, e2);
    // 8: layer 3 (items) + out epilogue
    int itemBlocks = (N_ITEMS * 32 + 255) / 256;
    k_spmm_items<<<itemBlocks, 256>>>(item_emb);

    // 9-10: MLPs
    k_items<<<(N_ITEMS + 63) / 64, 256>>>(pop_emb, bins, gW1, gb1, gW2, gb2,
                                          iW1, ib1, iW2, ib2);
    k_users<<<(BATCH * 32 + 255) / 256, 256>>>(users, user_emb, uW1, ub1, uW2, ub2);

    // 11: scores
    dim3 grid((N_ITEMS + 63) / 64, BATCH / 64);
    k_scores<<<grid, 256>>>(user_bias, item_bias, users, out);
}

// round 5
// speedup vs baseline: 1.5828x; 1.1206x over previous
#include <cuda_runtime.h>
#include <cuda_fp16.h>
#include <math.h>

#define N_USERS 100000
#define N_ITEMS 50000
#define N_NODES 150000
#define D       64
#define NNZ     2000000
#define BATCH   256
#define WL      0.25f   // 1/(N_LAYERS+1)

typedef unsigned long long u64t;
#define FULL 0xffffffffu

// ---------------- f32x2 packed-FMA helpers (sm_100+) -------------------------
__device__ __forceinline__ u64t pack2(float x, float y) {
    u64t r; asm("mov.b64 %0, {%1, %2};" : "=l"(r) : "f"(x), "f"(y)); return r;
}
__device__ __forceinline__ u64t pack1(float x) {
    u64t r; asm("mov.b64 %0, {%1, %1};" : "=l"(r) : "f"(x)); return r;
}
__device__ __forceinline__ void ffma2(u64t& d, u64t a, u64t b) {
    asm("fma.rn.f32x2 %0, %1, %2, %0;" : "+l"(d) : "l"(a), "l"(b));
}
__device__ __forceinline__ float2 unpack2(u64t v) {
    float2 f; asm("mov.b64 {%0, %1}, %2;" : "=f"(f.x), "=f"(f.y) : "l"(v)); return f;
}
__device__ __forceinline__ float2 h2f2(unsigned int h) {
    __half2 hh = *reinterpret_cast<__half2*>(&h);
    return __half22float2(hh);
}
__device__ __forceinline__ unsigned int f2h2(float x, float y) {
    __half2 hh = __floats2half2_rn(x, y);
    return *reinterpret_cast<unsigned int*>(&hh);
}

// ---------------- scratch (device globals) -----------------------------------
__device__ __align__(256) __half g_e1h[N_NODES * D];
__device__ __align__(256) __half g_e2h[N_NODES * D];   // also layer-1 input staging
__device__ __align__(256) float g_outI[N_ITEMS * D];
__device__ __align__(256) float g_I[N_ITEMS * D];
__device__ __align__(256) float g_U[BATCH * D];
__device__ int   g_rowptr[N_NODES + 1];
__device__ int   g_wcur[N_NODES];
__device__ int   g_counts[N_NODES];
__device__ int   g_bsum[256];
__device__ __align__(256) int2 g_csr[NNZ];

// ---------------- init: zero counts + stage concat embedding (fp16) -----------
__global__ void k_init(const float* __restrict__ ue, const float* __restrict__ ie) {
    int t = blockIdx.x * blockDim.x + threadIdx.x;   // float4 index
    const int NU4 = N_USERS * D / 4;
    const int NT4 = N_NODES * D / 4;
    if (t < NT4) {
        float4 v = (t < NU4) ? ((const float4*)ue)[t] : ((const float4*)ie)[t - NU4];
        ((uint2*)g_e2h)[t] = make_uint2(f2h2(v.x, v.y), f2h2(v.z, v.w));
    }
    if (t < N_NODES) g_counts[t] = 0;
}

// ---------------- CSR build ---------------------------------------------------
__global__ void k_hist(const int* __restrict__ rows) {
    int i = blockIdx.x * blockDim.x + threadIdx.x;
    if (i < NNZ) atomicAdd(&g_counts[rows[i]], 1);
}

__global__ void k_blockreduce() {
    __shared__ int wsum[32];
    int i = blockIdx.x * 1024 + threadIdx.x;
    int v = (i < N_NODES) ? g_counts[i] : 0;
#pragma unroll
    for (int off = 16; off > 0; off >>= 1) v += __shfl_down_sync(FULL, v, off);
    int wid = threadIdx.x >> 5, lane = threadIdx.x & 31;
    if (lane == 0) wsum[wid] = v;
    __syncthreads();
    if (wid == 0) {
        int s = wsum[lane];
#pragma unroll
        for (int off = 16; off > 0; off >>= 1) s += __shfl_down_sync(FULL, s, off);
        if (lane == 0) g_bsum[blockIdx.x] = s;
    }
}

__global__ void k_blockscan() {
    __shared__ int wsum[33];
    __shared__ int soff_sh;
    int tid = threadIdx.x;
    int wid = tid >> 5, lane = tid & 31;

    {
        int p = (tid < blockIdx.x && tid < 256) ? g_bsum[tid] : 0;
        if (tid < 256) {
#pragma unroll
            for (int off = 16; off > 0; off >>= 1) p += __shfl_down_sync(FULL, p, off);
            if (lane == 0) wsum[wid] = p;
        }
        __syncthreads();
        if (tid < 8) {
            int s = wsum[tid];
#pragma unroll
            for (int off = 4; off > 0; off >>= 1) s += __shfl_down_sync(0xffu, s, off);
            if (tid == 0) soff_sh = s;
        }
        __syncthreads();
    }

    int i = blockIdx.x * 1024 + tid;
    int v = (i < N_NODES) ? g_counts[i] : 0;
    int sc = v;
#pragma unroll
    for (int off = 1; off < 32; off <<= 1) {
        int t = __shfl_up_sync(FULL, sc, off);
        if (lane >= off) sc += t;
    }
    if (lane == 31) wsum[wid] = sc;
    __syncthreads();
    if (wid == 0) {
        int s = (lane < 32) ? wsum[lane] : 0;
#pragma unroll
        for (int off = 1; off < 32; off <<= 1) {
            int t = __shfl_up_sync(FULL, s, off);
            if (lane >= off) s += t;
        }
        wsum[lane + 1] = s;
        if (lane == 0) wsum[0] = 0;
    }
    __syncthreads();
    if (i < N_NODES) {
        int excl = sc - v + wsum[wid] + soff_sh;
        g_rowptr[i] = excl;
        g_wcur[i]   = excl;
    }
    if (i == 0) g_rowptr[N_NODES] = NNZ;
}

__global__ void k_scatter(const float* __restrict__ vals,
                          const int* __restrict__ rows,
                          const int* __restrict__ cols) {
    int i = blockIdx.x * blockDim.x + threadIdx.x;
    if (i < NNZ) {
        int r = rows[i];
        int pos = atomicAdd(&g_wcur[r], 1);
        g_csr[pos] = make_int2(cols[i], __float_as_int(vals[i]));
    }
}

// ---------------- SPMM (fp16 rows): half-warp per edge stream -----------------
// row = 64 halves = 16 uint2 chunks; lane j in [0,16) holds 4 halves.
__global__ void k_spmm(const uint2* __restrict__ ein, uint2* __restrict__ eout) {
    int w    = (blockIdx.x * blockDim.x + threadIdx.x) >> 5;
    int lane = threadIdx.x & 31;
    if (w >= N_NODES) return;
    int half = lane >> 4;
    int j    = lane & 15;
    int s = __ldg(&g_rowptr[w]), e = __ldg(&g_rowptr[w + 1]);

    u64t a01 = 0ull, a23 = 0ull;
    int i = s + half;
    for (; i + 6 < e; i += 8) {
        int2 c0 = __ldg(&g_csr[i]);
        int2 c1 = __ldg(&g_csr[i + 2]);
        int2 c2 = __ldg(&g_csr[i + 4]);
        int2 c3 = __ldg(&g_csr[i + 6]);
        uint2 x0 = __ldg(ein + (size_t)c0.x * 16 + j);
        uint2 x1 = __ldg(ein + (size_t)c1.x * 16 + j);
        uint2 x2 = __ldg(ein + (size_t)c2.x * 16 + j);
        uint2 x3 = __ldg(ein + (size_t)c3.x * 16 + j);
        u64t v0 = pack1(__int_as_float(c0.y)), v1 = pack1(__int_as_float(c1.y));
        u64t v2 = pack1(__int_as_float(c2.y)), v3 = pack1(__int_as_float(c3.y));
        float2 f;
        f = h2f2(x0.x); ffma2(a01, v0, pack2(f.x, f.y));
        f = h2f2(x0.y); ffma2(a23, v0, pack2(f.x, f.y));
        f = h2f2(x1.x); ffma2(a01, v1, pack2(f.x, f.y));
        f = h2f2(x1.y); ffma2(a23, v1, pack2(f.x, f.y));
        f = h2f2(x2.x); ffma2(a01, v2, pack2(f.x, f.y));
        f = h2f2(x2.y); ffma2(a23, v2, pack2(f.x, f.y));
        f = h2f2(x3.x); ffma2(a01, v3, pack2(f.x, f.y));
        f = h2f2(x3.y); ffma2(a23, v3, pack2(f.x, f.y));
    }
    for (; i < e; i += 2) {
        int2 c = __ldg(&g_csr[i]);
        uint2 x = __ldg(ein + (size_t)c.x * 16 + j);
        u64t v = pack1(__int_as_float(c.y));
        float2 f;
        f = h2f2(x.x); ffma2(a01, v, pack2(f.x, f.y));
        f = h2f2(x.y); ffma2(a23, v, pack2(f.x, f.y));
    }
    float2 lo = unpack2(a01), hi = unpack2(a23);
    float4 a = make_float4(lo.x, lo.y, hi.x, hi.y);
    a.x += __shfl_down_sync(FULL, a.x, 16);
    a.y += __shfl_down_sync(FULL, a.y, 16);
    a.z += __shfl_down_sync(FULL, a.z, 16);
    a.w += __shfl_down_sync(FULL, a.w, 16);
    if (half == 0)
        eout[(size_t)w * 16 + j] = make_uint2(f2h2(a.x, a.y), f2h2(a.z, a.w));
}

// ---------------- layer-3 SPMM: item rows only, fused out epilogue ------------
__global__ void k_spmm_items(const float* __restrict__ item_emb) {
    int w    = (blockIdx.x * blockDim.x + threadIdx.x) >> 5;
    int lane = threadIdx.x & 31;
    if (w >= N_ITEMS) return;
    int half = lane >> 4;
    int j    = lane & 15;
    int node = N_USERS + w;
    int s = __ldg(&g_rowptr[node]), e = __ldg(&g_rowptr[node + 1]);
    const uint2* ein = (const uint2*)g_e2h;

    u64t a01 = 0ull, a23 = 0ull;
    int i = s + half;
    for (; i + 6 < e; i += 8) {
        int2 c0 = __ldg(&g_csr[i]);
        int2 c1 = __ldg(&g_csr[i + 2]);
        int2 c2 = __ldg(&g_csr[i + 4]);
        int2 c3 = __ldg(&g_csr[i + 6]);
        uint2 x0 = __ldg(ein + (size_t)c0.x * 16 + j);
        uint2 x1 = __ldg(ein + (size_t)c1.x * 16 + j);
        uint2 x2 = __ldg(ein + (size_t)c2.x * 16 + j);
        uint2 x3 = __ldg(ein + (size_t)c3.x * 16 + j);
        u64t v0 = pack1(__int_as_float(c0.y)), v1 = pack1(__int_as_float(c1.y));
        u64t v2 = pack1(__int_as_float(c2.y)), v3 = pack1(__int_as_float(c3.y));
        float2 f;
        f = h2f2(x0.x); ffma2(a01, v0, pack2(f.x, f.y));
        f = h2f2(x0.y); ffma2(a23, v0, pack2(f.x, f.y));
        f = h2f2(x1.x); ffma2(a01, v1, pack2(f.x, f.y));
        f = h2f2(x1.y); ffma2(a23, v1, pack2(f.x, f.y));
        f = h2f2(x2.x); ffma2(a01, v2, pack2(f.x, f.y));
        f = h2f2(x2.y); ffma2(a23, v2, pack2(f.x, f.y));
        f = h2f2(x3.x); ffma2(a01, v3, pack2(f.x, f.y));
        f = h2f2(x3.y); ffma2(a23, v3, pack2(f.x, f.y));
    }
    for (; i < e; i += 2) {
        int2 c = __ldg(&g_csr[i]);
        uint2 x = __ldg(ein + (size_t)c.x * 16 + j);
        u64t v = pack1(__int_as_float(c.y));
        float2 f;
        f = h2f2(x.x); ffma2(a01, v, pack2(f.x, f.y));
        f = h2f2(x.y); ffma2(a23, v, pack2(f.x, f.y));
    }
    float2 lo = unpack2(a01), hi = unpack2(a23);
    float4 a = make_float4(lo.x, lo.y, hi.x, hi.y);
    a.x += __shfl_down_sync(FULL, a.x, 16);
    a.y += __shfl_down_sync(FULL, a.y, 16);
    a.z += __shfl_down_sync(FULL, a.z, 16);
    a.w += __shfl_down_sync(FULL, a.w, 16);
    if (half == 0) {
        float4 e0 = __ldg((const float4*)(item_emb + (size_t)w * D) + j);
        uint2 h1 = ((const uint2*)g_e1h)[(size_t)node * 16 + j];
        uint2 h2 = ((const uint2*)g_e2h)[(size_t)node * 16 + j];
        float2 x1a = h2f2(h1.x), x1b = h2f2(h1.y);
        float2 x2a = h2f2(h2.x), x2b = h2f2(h2.y);
        ((float4*)(g_outI + (size_t)w * D))[j] = make_float4(
            WL * (e0.x + x1a.x + x2a.x + a.x), WL * (e0.y + x1a.y + x2a.y + a.y),
            WL * (e0.z + x1b.x + x2b.x + a.z), WL * (e0.w + x1b.y + x2b.y + a.w));
    }
}

// ---------------- items: tiled GEMM chain (64 items/block, f32x2) -------------
__global__ __launch_bounds__(256) void k_items(
        const float* __restrict__ pop_emb, const int* __restrict__ bins,
        const float* __restrict__ gW1, const float* __restrict__ gb1,
        const float* __restrict__ gW2, const float* __restrict__ gb2,
        const float* __restrict__ iW1, const float* __restrict__ ib1,
        const float* __restrict__ iW2, const float* __restrict__ ib2) {
    __shared__ float at[64][68];
    __shared__ float xt[64][68];
    int tid = threadIdx.x;
    int tx  = tid & 15;
    int ty  = tid >> 4;
    int it0 = blockIdx.x * 64;

    for (int idx = tid; idx < 64 * 64; idx += 256) {
        int item = idx >> 6, k = idx & 63;
        int it = it0 + item;
        float a = 0.f; int b = 0;
        if (it < N_ITEMS) { a = g_outI[(size_t)it * D + k]; b = __ldg(&bins[it]); }
        at[k][item] = a;
        xt[k][item] = __ldg(&pop_emb[b * D + k]);
    }
    __syncthreads();

    u64t h01[4] = {0, 0, 0, 0}, h23[4] = {0, 0, 0, 0};
#pragma unroll 8
    for (int k = 0; k < 64; k++) {
        float4 xa = *(const float4*)&at[k][ty * 4];
        float4 w  = __ldg((const float4*)&gW1[k * 64 + tx * 4]);
        u64t w01 = pack2(w.x, w.y), w23 = pack2(w.z, w.w);
        u64t x0 = pack1(xa.x), x1 = pack1(xa.y), x2 = pack1(xa.z), x3 = pack1(xa.w);
        ffma2(h01[0], x0, w01); ffma2(h23[0], x0, w23);
        ffma2(h01[1], x1, w01); ffma2(h23[1], x1, w23);
        ffma2(h01[2], x2, w01); ffma2(h23[2], x2, w23);
        ffma2(h01[3], x3, w01); ffma2(h23[3], x3, w23);
    }
#pragma unroll 8
    for (int k = 0; k < 64; k++) {
        float4 xa = *(const float4*)&xt[k][ty * 4];
        float4 w  = __ldg((const float4*)&gW1[(64 + k) * 64 + tx * 4]);
        u64t w01 = pack2(w.x, w.y), w23 = pack2(w.z, w.w);
        u64t x0 = pack1(xa.x), x1 = pack1(xa.y), x2 = pack1(xa.z), x3 = pack1(xa.w);
        ffma2(h01[0], x0, w01); ffma2(h23[0], x0, w23);
        ffma2(h01[1], x1, w01); ffma2(h23[1], x1, w23);
        ffma2(h01[2], x2, w01); ffma2(h23[2], x2, w23);
        ffma2(h01[3], x3, w01); ffma2(h23[3], x3, w23);
    }

    float4 b1 = __ldg((const float4*)&gb1[tx * 4]);
    float4 w2 = __ldg((const float4*)&gW2[tx * 4]);
    float gb2v = __ldg(gb2);
    float z[4];
#pragma unroll
    for (int r = 0; r < 4; r++) {
        float2 hA = unpack2(h01[r]);
        float2 hB = unpack2(h23[r]);
        float t = fmaxf(hA.x + b1.x, 0.f) * w2.x + fmaxf(hA.y + b1.y, 0.f) * w2.y
                + fmaxf(hB.x + b1.z, 0.f) * w2.z + fmaxf(hB.y + b1.w, 0.f) * w2.w;
#pragma unroll
        for (int off = 8; off > 0; off >>= 1) t += __shfl_xor_sync(FULL, t, off);
        z[r] = 1.f / (1.f + expf(-(t + gb2v)));
    }
    __syncthreads();

#pragma unroll
    for (int jj = 0; jj < 4; jj++) {
        int j = tx * 4 + jj;
        float4 av = *(const float4*)&at[j][ty * 4];
        float4 pv = *(const float4*)&xt[j][ty * 4];
        float4 f;
        f.x = (1.f - z[0]) * av.x + z[0] * pv.x;
        f.y = (1.f - z[1]) * av.y + z[1] * pv.y;
        f.z = (1.f - z[2]) * av.z + z[2] * pv.z;
        f.w = (1.f - z[3]) * av.w + z[3] * pv.w;
        *(float4*)&xt[j][ty * 4] = f;
    }
    __syncthreads();

    u64t q01[4] = {0, 0, 0, 0}, q23[4] = {0, 0, 0, 0};
#pragma unroll 8
    for (int k = 0; k < 64; k++) {
        float4 xa = *(const float4*)&xt[k][ty * 4];
        float4 w  = __ldg((const float4*)&iW1[k * 64 + tx * 4]);
        u64t w01 = pack2(w.x, w.y), w23 = pack2(w.z, w.w);
        u64t x0 = pack1(xa.x), x1 = pack1(xa.y), x2 = pack1(xa.z), x3 = pack1(xa.w);
        ffma2(q01[0], x0, w01); ffma2(q23[0], x0, w23);
        ffma2(q01[1], x1, w01); ffma2(q23[1], x1, w23);
        ffma2(q01[2], x2, w01); ffma2(q23[2], x2, w23);
        ffma2(q01[3], x3, w01); ffma2(q23[3], x3, w23);
    }
    {
        float4 bi = __ldg((const float4*)&ib1[tx * 4]);
        float qv[4][4];
#pragma unroll
        for (int r = 0; r < 4; r++) {
            float2 qA = unpack2(q01[r]);
            float2 qB = unpack2(q23[r]);
            qv[r][0] = fmaxf(qA.x + bi.x, 0.f);
            qv[r][1] = fmaxf(qA.y + bi.y, 0.f);
            qv[r][2] = fmaxf(qB.x + bi.z, 0.f);
            qv[r][3] = fmaxf(qB.y + bi.w, 0.f);
        }
        __syncthreads();
#pragma unroll
        for (int cc = 0; cc < 4; cc++)
            *(float4*)&at[tx * 4 + cc][ty * 4] =
                make_float4(qv[0][cc], qv[1][cc], qv[2][cc], qv[3][cc]);
    }
    __syncthreads();

    u64t y01[4] = {0, 0, 0, 0}, y23[4] = {0, 0, 0, 0};
#pragma unroll 8
    for (int k = 0; k < 64; k++) {
        float4 xa = *(const float4*)&at[k][ty * 4];
        float4 w  = __ldg((const float4*)&iW2[k * 64 + tx * 4]);
        u64t w01 = pack2(w.x, w.y), w23 = pack2(w.z, w.w);
        u64t x0 = pack1(xa.x), x1 = pack1(xa.y), x2 = pack1(xa.z), x3 = pack1(xa.w);
        ffma2(y01[0], x0, w01); ffma2(y23[0], x0, w23);
        ffma2(y01[1], x1, w01); ffma2(y23[1], x1, w23);
        ffma2(y01[2], x2, w01); ffma2(y23[2], x2, w23);
        ffma2(y01[3], x3, w01); ffma2(y23[3], x3, w23);
    }
    float4 bo = __ldg((const float4*)&ib2[tx * 4]);
#pragma unroll
    for (int r = 0; r < 4; r++) {
        int item = it0 + ty * 4 + r;
        if (item < N_ITEMS) {
            float2 yA = unpack2(y01[r]);
            float2 yB = unpack2(y23[r]);
            *(float4*)&g_I[(size_t)item * D + tx * 4] =
                make_float4(yA.x + bo.x, yA.y + bo.y, yB.x + bo.z, yB.y + bo.w);
        }
    }
}

// ---------------- users: e3 row + out + MLP (warp per user) -------------------
__global__ void k_users(const int* __restrict__ users, const float* __restrict__ user_emb,
                        const float* __restrict__ uW1, const float* __restrict__ ub1,
                        const float* __restrict__ uW2, const float* __restrict__ ub2) {
    int w    = (blockIdx.x * blockDim.x + threadIdx.x) >> 5;
    int lane = threadIdx.x & 31;
    if (w >= BATCH) return;
    int u = __ldg(&users[w]);
    int s = __ldg(&g_rowptr[u]), e = __ldg(&g_rowptr[u + 1]);
    float ax = 0.f, ay = 0.f;
    const __half2* e2h2 = (const __half2*)g_e2h;
    for (int i = s; i < e; i++) {
        int2 c = __ldg(&g_csr[i]);
        float2 x = __half22float2(e2h2[(size_t)c.x * 32 + lane]);
        float v = __int_as_float(c.y);
        ax += v * x.x; ay += v * x.y;
    }
    float2 e0 = ((const float2*)(user_emb + (size_t)u * D))[lane];
    float2 x1 = __half22float2(((const __half2*)g_e1h)[(size_t)u * 32 + lane]);
    float2 x2 = __half22float2(((const __half2*)g_e2h)[(size_t)u * 32 + lane]);
    float xx = WL * (e0.x + x1.x + x2.x + ax);
    float xy = WL * (e0.y + x1.y + x2.y + ay);

    const float2* W1 = (const float2*)uW1;
    float hx = 0.f, hy = 0.f;
#pragma unroll 8
    for (int m = 0; m < 32; m++) {
        float2 wA = W1[(2 * m) * 32 + lane];
        float2 wB = W1[(2 * m + 1) * 32 + lane];
        float xA = __shfl_sync(FULL, xx, m);
        float xB = __shfl_sync(FULL, xy, m);
        hx += xA * wA.x + xB * wB.x;
        hy += xA * wA.y + xB * wB.y;
    }
    float2 b1 = ((const float2*)ub1)[lane];
    hx = fmaxf(hx + b1.x, 0.f);
    hy = fmaxf(hy + b1.y, 0.f);

    const float2* W2 = (const float2*)uW2;
    float yx = 0.f, yy = 0.f;
#pragma unroll 8
    for (int m = 0; m < 32; m++) {
        float2 wA = W2[(2 * m) * 32 + lane];
        float2 wB = W2[(2 * m + 1) * 32 + lane];
        float xA = __shfl_sync(FULL, hx, m);
        float xB = __shfl_sync(FULL, hy, m);
        yx += xA * wA.x + xB * wB.x;
        yy += xA * wA.y + xB * wB.y;
    }
    float2 b2 = ((const float2*)ub2)[lane];
    ((float2*)(g_U + (size_t)w * D))[lane] = make_float2(yx + b2.x, yy + b2.y);
}

// ---------------- scores: [256,64] @ [50000,64]^T + biases (f32x2) ------------
__global__ __launch_bounds__(256) void k_scores(
        const float* __restrict__ user_bias,
        const float* __restrict__ item_bias,
        const int* __restrict__ users,
        float* __restrict__ out) {
    __shared__ float UsT[64][68];
    __shared__ float IsT[64][68];
    int tid = threadIdx.x;
    int tx = tid & 15;
    int ty = tid >> 4;
    int m0 = blockIdx.y * 64;
    int n0 = blockIdx.x * 64;

    for (int idx = tid; idx < 64 * 64; idx += 256) {
        int row = idx >> 6, k = idx & 63;
        UsT[k][row] = g_U[(size_t)(m0 + row) * D + k];
        int n = n0 + row;
        IsT[k][row] = (n < N_ITEMS) ? g_I[(size_t)n * D + k] : 0.f;
    }
    __syncthreads();

    u64t a01[4] = {0, 0, 0, 0}, a23[4] = {0, 0, 0, 0};
#pragma unroll 8
    for (int k = 0; k < 64; k++) {
        float4 uu = *(const float4*)&UsT[k][ty * 4];
        float4 vv = *(const float4*)&IsT[k][tx * 4];
        u64t v01 = pack2(vv.x, vv.y), v23 = pack2(vv.z, vv.w);
        u64t u0 = pack1(uu.x), u1 = pack1(uu.y), u2 = pack1(uu.z), u3 = pack1(uu.w);
        ffma2(a01[0], u0, v01); ffma2(a23[0], u0, v23);
        ffma2(a01[1], u1, v01); ffma2(a23[1], u1, v23);
        ffma2(a01[2], u2, v01); ffma2(a23[2], u2, v23);
        ffma2(a01[3], u3, v01); ffma2(a23[3], u3, v23);
    }

    int n = n0 + tx * 4;
    if (n < N_ITEMS) {
        float4 ibv = *(const float4*)&item_bias[n];
#pragma unroll
        for (int r = 0; r < 4; r++) {
            int m = m0 + ty * 4 + r;
            float ub = __ldg(&user_bias[__ldg(&users[m])]);
            float2 sA = unpack2(a01[r]);
            float2 sB = unpack2(a23[r]);
            *(float4*)&out[(size_t)m * N_ITEMS + n] =
                make_float4(sA.x + ub + ibv.x, sA.y + ub + ibv.y,
                            sB.x + ub + ibv.z, sB.y + ub + ibv.w);
        }
    }
}

// ---------------- launch -------------------------------------------------------
extern "C" void kernel_launch(void* const* d_in, const int* in_sizes, int n_in,
                              void* d_out, int out_size) {
    const float* user_emb  = (const float*)d_in[0];
    const float* item_emb  = (const float*)d_in[1];
    const float* user_bias = (const float*)d_in[2];
    const float* item_bias = (const float*)d_in[3];
    const float* pop_emb   = (const float*)d_in[4];
    const float* uW1 = (const float*)d_in[5];
    const float* ub1 = (const float*)d_in[6];
    const float* uW2 = (const float*)d_in[7];
    const float* ub2 = (const float*)d_in[8];
    const float* iW1 = (const float*)d_in[9];
    const float* ib1 = (const float*)d_in[10];
    const float* iW2 = (const float*)d_in[11];
    const float* ib2 = (const float*)d_in[12];
    const float* gW1 = (const float*)d_in[13];
    const float* gb1 = (const float*)d_in[14];
    const float* gW2 = (const float*)d_in[15];
    const float* gb2 = (const float*)d_in[16];
    const float* adj_vals = (const float*)d_in[17];
    const int*   adj_rows = (const int*)d_in[18];
    const int*   adj_cols = (const int*)d_in[19];
    const int*   bins     = (const int*)d_in[20];
    const int*   users    = (const int*)d_in[21];
    float* out = (float*)d_out;

    uint2* e1h; cudaGetSymbolAddress((void**)&e1h, g_e1h);
    uint2* e2h; cudaGetSymbolAddress((void**)&e2h, g_e2h);

    // init (zero counts + stage fp16 embeddings into e2h)
    k_init<<<(N_NODES * D / 4 + 255) / 256, 256>>>(user_emb, item_emb);
    // CSR build
    k_hist<<<(NNZ + 255) / 256, 256>>>(adj_rows);
    int nb = (N_NODES + 1023) / 1024;
    k_blockreduce<<<nb, 1024>>>();
    k_blockscan<<<nb, 1024>>>();
    k_scatter<<<(NNZ + 255) / 256, 256>>>(adj_vals, adj_rows, adj_cols);

    int fullBlocks = (N_NODES * 32 + 255) / 256;
    k_spmm<<<fullBlocks, 256>>>(e2h, e1h);          // layer 1
    k_spmm<<<fullBlocks, 256>>>(e1h, e2h);          // layer 2
    int itemBlocks = (N_ITEMS * 32 + 255) / 256;
    k_spmm_items<<<itemBlocks, 256>>>(item_emb);    // layer 3 (items) + epilogue

    k_items<<<(N_ITEMS + 63) / 64, 256>>>(pop_emb, bins, gW1, gb1, gW2, gb2,
                                          iW1, ib1, iW2, ib2);
    k_users<<<(BATCH * 32 + 255) / 256, 256>>>(users, user_emb, uW1, ub1, uW2, ub2);

    dim3 grid((N_ITEMS + 63) / 64, BATCH / 64);
    k_scores<<<grid, 256>>>(user_bias, item_bias, users, out);
}